// round 8
// baseline (speedup 1.0000x reference)
#include <cuda_runtime.h>
#include <cuda_bf16.h>
#include <math.h>
#include <stdint.h>

#define DI __device__ __forceinline__

// Fixed problem shapes (b=2, h=w=128, d=256, ns=4, f=4)
static constexpr int TOK  = 32768;
static constexpr int D    = 256;
static constexpr int L    = 1024;
static constexpr int NWIN = 32;
static constexpr int HID  = 2048;

typedef __nv_bfloat16 bf16;

// ===================== PTX helpers (base sm_103 legal: sm_80 era) ===========
DI uint32_t smem_to_u32(const void* p) {
    uint32_t a;
    asm("{ .reg .u64 t; cvta.to.shared.u64 t, %1; cvt.u32.u64 %0, t; }"
        : "=r"(a) : "l"(p));
    return a;
}
DI void ldsm4(uint32_t* r, uint32_t addr) {
    asm volatile("ldmatrix.sync.aligned.m8n8.x4.shared.b16 {%0,%1,%2,%3}, [%4];"
                 : "=r"(r[0]), "=r"(r[1]), "=r"(r[2]), "=r"(r[3]) : "r"(addr));
}
DI void mma_bf16(float* d, const uint32_t* a, const uint32_t* b) {
    asm volatile("mma.sync.aligned.m16n8k16.row.col.f32.bf16.bf16.f32 "
                 "{%0,%1,%2,%3}, {%4,%5,%6,%7}, {%8,%9}, {%0,%1,%2,%3};"
                 : "+f"(d[0]), "+f"(d[1]), "+f"(d[2]), "+f"(d[3])
                 : "r"(a[0]), "r"(a[1]), "r"(a[2]), "r"(a[3]), "r"(b[0]), "r"(b[1]));
}
DI void mma_s8(int* d, const uint32_t* a, const uint32_t* b) {
    asm volatile("mma.sync.aligned.m16n8k32.row.col.s32.s8.s8.s32 "
                 "{%0,%1,%2,%3}, {%4,%5,%6,%7}, {%8,%9}, {%0,%1,%2,%3};"
                 : "+r"(d[0]), "+r"(d[1]), "+r"(d[2]), "+r"(d[3])
                 : "r"(a[0]), "r"(a[1]), "r"(a[2]), "r"(a[3]), "r"(b[0]), "r"(b[1]));
}
DI void cpasync16(uint32_t dst, const void* src) {
    asm volatile("cp.async.cg.shared.global [%0], [%1], 16;" :: "r"(dst), "l"(src));
}
DI void cpcommit() { asm volatile("cp.async.commit_group;" ::: "memory"); }
template<int N> DI void cpwait() { asm volatile("cp.async.wait_group %0;" :: "n"(N) : "memory"); }

// ===================== index math + misc ====================================
DI int gather_win(int r) {
    int w = r >> 10, p = r & 1023;
    int b = w >> 4, wi = (w >> 2) & 3, wj = w & 3;
    int rr = p >> 5, cc = p & 31;
    int i = (wi * 32 + rr + 16) & 127;
    int j = (wj * 32 + cc + 16) & 127;
    return (b << 14) + (i << 7) + j;
}
DI float gelu_exact(float x) { return 0.5f * x * (1.0f + erff(x * 0.70710678118654752f)); }
DI void split_bf16(float x, bf16& h, bf16& l) {
    h = __float2bfloat16(x);
    l = __float2bfloat16(x - __bfloat162float(h));
}

// ===================== device scratch (no allocations) ======================
__device__ __align__(16) bf16 g_swh[TOK * D],  g_swl[TOK * D];     // source, window order
__device__ __align__(16) bf16 g_twh[TOK * D],  g_twl[TOK * D];     // target, window order
__device__ __align__(16) bf16 g_qh[TOK * D],   g_ql[TOK * D];      // Q/16, window order
__device__ __align__(16) bf16 g_kh[TOK * D],   g_kl[TOK * D];
__device__ __align__(16) bf16 g_vth[TOK * D],  g_vtl[TOK * D];     // V^T per window
__device__ __align__(16) bf16 g_ah[TOK * D],   g_al[TOK * D];      // attn out (window order)
__device__ float g_msg[TOK * D];
__device__ float g_msgln[TOK * D];                                  // LN1 out, token order
__device__ float g_hidf[(size_t)TOK * HID];                         // MLP1 out fp32 (256 MB)
__device__ float g_msg2[TOK * D];
__device__ __align__(16) bf16 g_wqh[D * D], g_wql[D * D];
__device__ __align__(16) bf16 g_wkvh[512 * D], g_wkvl[512 * D];    // [Wk^T ; Wv^T]
__device__ __align__(16) bf16 g_wmh[D * D], g_wml[D * D];
__device__ float g_w1tf[HID * 512];                                 // W1^T fp32
__device__ float g_w2tf[D * HID];                                   // W2^T fp32
// int8 slices + per-row scales
__device__ __align__(16) int8_t g_hc1[TOK * 512],  g_hc2[TOK * 512];
__device__ __align__(16) int8_t g_hd1[(size_t)TOK * HID], g_hd2[(size_t)TOK * HID];
__device__ __align__(16) int8_t g_w1q1[HID * 512], g_w1q2[HID * 512];
__device__ __align__(16) int8_t g_w2q1[D * HID],   g_w2q2[D * HID];
__device__ float g_sahc[TOK], g_sahd[TOK], g_sbw1[HID], g_sbw2[D];

// ===================== bf16 HMMA GEMM (3-pass hi/lo) ========================
static constexpr int TILE_B  = 10240;   // 128 rows * 80B
static constexpr int STAGE_B = 4 * TILE_B;
static constexpr int SMEM_BYTES = 2 * STAGE_B;  // 81920

DI void stage_load(uint32_t sdst,
                   const bf16* __restrict__ Ah, const bf16* __restrict__ Al,
                   const bf16* __restrict__ Bh, const bf16* __restrict__ Bl,
                   int arow, int brow, int K, int k0, int t) {
    #pragma unroll
    for (int h = 0; h < 2; h++) {
        const int idx = t + h * 256;
        const int r = idx >> 2, c = (idx & 3) << 3;
        const uint32_t so = sdst + r * 80 + c * 2;
        const long long ga = (long long)(arow + r) * K + k0 + c;
        const long long gb = (long long)(brow + r) * K + k0 + c;
        cpasync16(so,              Ah + ga);
        cpasync16(so + TILE_B,     Al + ga);
        cpasync16(so + 2 * TILE_B, Bh + gb);
        cpasync16(so + 3 * TILE_B, Bl + gb);
    }
}

// EPI: 0=fp32, 5=bf16 hi/lo scaled 1/16 (Q), 6=K hi/lo | V^T window combined
template<int EPI>
__global__ void __launch_bounds__(256, 2)
gemm_mma(const bf16* __restrict__ Ahi, const bf16* __restrict__ Alo,
         const bf16* __restrict__ Bhi, const bf16* __restrict__ Blo,
         float* __restrict__ Cf, bf16* __restrict__ Chi, bf16* __restrict__ Clo,
         int M, int N, int K, long long sA, long long sB, long long sC)
{
    extern __shared__ __align__(128) char sm[];
    const uint32_t sb = smem_to_u32(sm);
    const int t = threadIdx.x, lane = t & 31, wid = t >> 5;
    const int wm = wid >> 2, wn = wid & 3;
    const int bn = blockIdx.x, bm = blockIdx.y, bz = blockIdx.z;
    Ahi += (long long)bz * sA; Alo += (long long)bz * sA;
    Bhi += (long long)bz * sB; Blo += (long long)bz * sB;
    const int arow = bm * 128, brow = bn * 128;

    const uint32_t aoff = (uint32_t)((wm * 64 + (lane & 7) + ((lane >> 3) & 1) * 8) * 80
                                     + (((lane >> 4) & 1) * 8) * 2);
    const uint32_t boff = (uint32_t)((wn * 32 + (lane & 7) + ((lane >> 4) & 1) * 8) * 80
                                     + (((lane >> 3) & 1) * 8) * 2);

    float acc[4][4][4];
    #pragma unroll
    for (int i = 0; i < 4; i++)
        #pragma unroll
        for (int j = 0; j < 4; j++)
            #pragma unroll
            for (int e = 0; e < 4; e++) acc[i][j][e] = 0.0f;

    const int NC = K >> 5;
    stage_load(sb, Ahi, Alo, Bhi, Blo, arow, brow, K, 0, t);
    cpcommit();

    for (int c = 0; c < NC; c++) {
        const uint32_t cur = sb + (uint32_t)(c & 1) * STAGE_B;
        if (c + 1 < NC) {
            stage_load(sb + (uint32_t)((c + 1) & 1) * STAGE_B,
                       Ahi, Alo, Bhi, Blo, arow, brow, K, (c + 1) << 5, t);
            cpcommit();
            cpwait<1>();
        } else {
            cpwait<0>();
        }
        __syncthreads();

        #pragma unroll
        for (int k16 = 0; k16 < 2; k16++) {
            uint32_t ah[4][4], al[4][4], bh[2][4], bl[2][4];
            #pragma unroll
            for (int mi = 0; mi < 4; mi++) {
                ldsm4(ah[mi], cur + aoff + mi * (16 * 80) + k16 * 32);
                ldsm4(al[mi], cur + TILE_B + aoff + mi * (16 * 80) + k16 * 32);
            }
            #pragma unroll
            for (int p = 0; p < 2; p++) {
                ldsm4(bh[p], cur + 2 * TILE_B + boff + p * (16 * 80) + k16 * 32);
                ldsm4(bl[p], cur + 3 * TILE_B + boff + p * (16 * 80) + k16 * 32);
            }
            #pragma unroll
            for (int mi = 0; mi < 4; mi++)
                #pragma unroll
                for (int ni = 0; ni < 4; ni++) {
                    const uint32_t* fh = &bh[ni >> 1][(ni & 1) * 2];
                    const uint32_t* fl = &bl[ni >> 1][(ni & 1) * 2];
                    mma_bf16(acc[mi][ni], ah[mi], fh);
                    mma_bf16(acc[mi][ni], ah[mi], fl);
                    mma_bf16(acc[mi][ni], al[mi], fh);
                }
        }
        __syncthreads();
    }

    const int group = lane >> 2, tid4 = lane & 3;
    #pragma unroll
    for (int mi = 0; mi < 4; mi++) {
        #pragma unroll
        for (int ni = 0; ni < 4; ni++) {
            const int r0 = bm * 128 + wm * 64 + mi * 16 + group;
            const int c0 = bn * 128 + wn * 32 + ni * 8 + tid4 * 2;
            const float* d = acc[mi][ni];
            if (EPI == 0) {
                float* Cp = Cf + (long long)bz * sC;
                *(float2*)(Cp + (long long)r0 * N + c0)       = make_float2(d[0], d[1]);
                *(float2*)(Cp + (long long)(r0 + 8) * N + c0) = make_float2(d[2], d[3]);
            } else if (EPI == 5) {
                #pragma unroll
                for (int rr = 0; rr < 2; rr++) {
                    float f0 = d[rr * 2] * 0.0625f, f1 = d[rr * 2 + 1] * 0.0625f;
                    bf16 h0, l0, h1, l1;
                    split_bf16(f0, h0, l0);
                    split_bf16(f1, h1, l1);
                    const long long base = (long long)bz * sC + (long long)(r0 + rr * 8) * N + c0;
                    __nv_bfloat162 hh; hh.x = h0; hh.y = h1;
                    __nv_bfloat162 ll; ll.x = l0; ll.y = l1;
                    *(__nv_bfloat162*)(Chi + base) = hh;
                    *(__nv_bfloat162*)(Clo + base) = ll;
                }
            } else { // EPI == 6
                if (c0 < 256) {
                    #pragma unroll
                    for (int rr = 0; rr < 2; rr++) {
                        bf16 h0, l0, h1, l1;
                        split_bf16(d[rr * 2], h0, l0);
                        split_bf16(d[rr * 2 + 1], h1, l1);
                        const long long base = (long long)(r0 + rr * 8) * 256 + c0;
                        __nv_bfloat162 hh; hh.x = h0; hh.y = h1;
                        __nv_bfloat162 ll; ll.x = l0; ll.y = l1;
                        *(__nv_bfloat162*)(Chi + base) = hh;
                        *(__nv_bfloat162*)(Clo + base) = ll;
                    }
                } else {
                    #pragma unroll
                    for (int rr = 0; rr < 2; rr++) {
                        const int r = r0 + rr * 8;
                        const int win = r >> 10, ml = r & 1023;
                        #pragma unroll
                        for (int e = 0; e < 2; e++) {
                            bf16 hh, ll;
                            split_bf16(d[rr * 2 + e], hh, ll);
                            const long long o = (long long)win * 262144
                                              + (long long)(c0 - 256 + e) * 1024 + ml;
                            g_vth[o] = hh; g_vtl[o] = ll;
                        }
                    }
                }
            }
        }
    }
}

// ===================== int8 IMMA GEMM (2-slice Ozaki, 3 passes) =============
// C[M,N] = sa_i*sb_j*(A1B1 + (A1B2+A2B1)/128); same tiling as bf16 kernel.
DI void stage_load_i8(uint32_t sdst,
                      const int8_t* __restrict__ A1, const int8_t* __restrict__ A2,
                      const int8_t* __restrict__ B1, const int8_t* __restrict__ B2,
                      int arow, int brow, int K, int k0, int t) {
    #pragma unroll
    for (int h = 0; h < 2; h++) {
        const int idx = t + h * 256;
        const int r = idx >> 2, c = (idx & 3) << 4;   // bytes within 64B row-chunk
        const uint32_t so = sdst + r * 80 + c;
        const long long ga = (long long)(arow + r) * K + k0 + c;
        const long long gb = (long long)(brow + r) * K + k0 + c;
        cpasync16(so,              A1 + ga);
        cpasync16(so + TILE_B,     A2 + ga);
        cpasync16(so + 2 * TILE_B, B1 + gb);
        cpasync16(so + 3 * TILE_B, B2 + gb);
    }
}

// EPI: 0 = scale -> fp32, 1 = scale -> GELU -> fp32
template<int EPI>
__global__ void __launch_bounds__(256, 1)
gemm_i8(const int8_t* __restrict__ A1, const int8_t* __restrict__ A2,
        const int8_t* __restrict__ B1, const int8_t* __restrict__ B2,
        const float* __restrict__ sa, const float* __restrict__ sbv,
        float* __restrict__ Cf, int M, int N, int K)
{
    extern __shared__ __align__(128) char sm[];
    const uint32_t sb = smem_to_u32(sm);
    const int t = threadIdx.x, lane = t & 31, wid = t >> 5;
    const int wm = wid >> 2, wn = wid & 3;
    const int bn = blockIdx.x, bm = blockIdx.y;
    const int arow = bm * 128, brow = bn * 128;

    const uint32_t aoff = (uint32_t)((wm * 64 + (lane & 7) + ((lane >> 3) & 1) * 8) * 80
                                     + ((lane >> 4) & 1) * 16);
    const uint32_t boff = (uint32_t)((wn * 32 + (lane & 7) + ((lane >> 4) & 1) * 8) * 80
                                     + ((lane >> 3) & 1) * 16);

    int acc1[4][4][4], acc2[4][4][4];
    #pragma unroll
    for (int i = 0; i < 4; i++)
        #pragma unroll
        for (int j = 0; j < 4; j++)
            #pragma unroll
            for (int e = 0; e < 4; e++) { acc1[i][j][e] = 0; acc2[i][j][e] = 0; }

    const int NC = K >> 6;                    // 64 int8 per chunk
    stage_load_i8(sb, A1, A2, B1, B2, arow, brow, K, 0, t);
    cpcommit();

    for (int c = 0; c < NC; c++) {
        const uint32_t cur = sb + (uint32_t)(c & 1) * STAGE_B;
        if (c + 1 < NC) {
            stage_load_i8(sb + (uint32_t)((c + 1) & 1) * STAGE_B,
                          A1, A2, B1, B2, arow, brow, K, (c + 1) << 6, t);
            cpcommit();
            cpwait<1>();
        } else {
            cpwait<0>();
        }
        __syncthreads();

        #pragma unroll
        for (int kk = 0; kk < 2; kk++) {      // 2 x k32
            uint32_t a1f[4][4], a2f[4][4], b1f[2][4], b2f[2][4];
            #pragma unroll
            for (int mi = 0; mi < 4; mi++) {
                ldsm4(a1f[mi], cur + aoff + mi * (16 * 80) + kk * 32);
                ldsm4(a2f[mi], cur + TILE_B + aoff + mi * (16 * 80) + kk * 32);
            }
            #pragma unroll
            for (int p = 0; p < 2; p++) {
                ldsm4(b1f[p], cur + 2 * TILE_B + boff + p * (16 * 80) + kk * 32);
                ldsm4(b2f[p], cur + 3 * TILE_B + boff + p * (16 * 80) + kk * 32);
            }
            #pragma unroll
            for (int mi = 0; mi < 4; mi++)
                #pragma unroll
                for (int ni = 0; ni < 4; ni++) {
                    const uint32_t* f1 = &b1f[ni >> 1][(ni & 1) * 2];
                    const uint32_t* f2 = &b2f[ni >> 1][(ni & 1) * 2];
                    mma_s8(acc1[mi][ni], a1f[mi], f1);
                    mma_s8(acc2[mi][ni], a1f[mi], f2);
                    mma_s8(acc2[mi][ni], a2f[mi], f1);
                }
        }
        __syncthreads();
    }

    const int group = lane >> 2, tid4 = lane & 3;
    #pragma unroll
    for (int mi = 0; mi < 4; mi++) {
        #pragma unroll
        for (int ni = 0; ni < 4; ni++) {
            const int r0 = bm * 128 + wm * 64 + mi * 16 + group;
            const int c0 = bn * 128 + wn * 32 + ni * 8 + tid4 * 2;
            const float sb0 = sbv[c0], sb1 = sbv[c0 + 1];
            #pragma unroll
            for (int rr = 0; rr < 2; rr++) {
                const int row = r0 + rr * 8;
                const float s = sa[row];
                float f0 = ((float)acc1[mi][ni][rr * 2]     + (float)acc2[mi][ni][rr * 2]     * 0.0078125f) * s * sb0;
                float f1 = ((float)acc1[mi][ni][rr * 2 + 1] + (float)acc2[mi][ni][rr * 2 + 1] * 0.0078125f) * s * sb1;
                if (EPI == 1) { f0 = gelu_exact(f0); f1 = gelu_exact(f1); }
                *(float2*)(Cf + (long long)row * N + c0) = make_float2(f0, f1);
            }
        }
    }
}

// ===================== fused flash attention (bf16, unchanged) ==============
static constexpr int FA_QH   = 0;
static constexpr int FA_QL   = 33792;
static constexpr int FA_K    = 67584;
static constexpr int FA_V    = 108544;
static constexpr int FA_P    = 190464;
static constexpr int FA_RED  = 225280;
static constexpr int FA_SMEM = 226304;

DI void fa_load_k(uint32_t sb, int stage, const bf16* __restrict__ Kh,
                  const bf16* __restrict__ Kl, int win, int kt, int dc, int t) {
    const long long base = (long long)win * 1024 + kt * 128;
    const uint32_t d0 = sb + FA_K + (uint32_t)stage * 20480;
    #pragma unroll
    for (int i = 0; i < 2; i++) {
        const int idx = t + i * 256;
        const int r = idx >> 2, c16 = idx & 3;
        const long long g = (base + r) * 256 + dc * 32 + c16 * 8;
        cpasync16(d0 + r * 80 + c16 * 16,         Kh + g);
        cpasync16(d0 + 10240 + r * 80 + c16 * 16, Kl + g);
    }
    cpcommit();
}
DI void fa_load_v(uint32_t sb, int stage, const bf16* __restrict__ Vh,
                  const bf16* __restrict__ Vl, int win, int kt, int vc, int t) {
    const uint32_t d0 = sb + FA_V + (uint32_t)stage * 40960;
    const long long base = (long long)win * 262144;
    #pragma unroll
    for (int i = 0; i < 4; i++) {
        const int idx = t + i * 256;
        const int r = idx >> 2, c16 = idx & 3;
        const long long g = base + (long long)r * 1024 + kt * 128 + vc * 32 + c16 * 8;
        cpasync16(d0 + r * 80 + c16 * 16,         Vh + g);
        cpasync16(d0 + 20480 + r * 80 + c16 * 16, Vl + g);
    }
    cpcommit();
}

__global__ void __launch_bounds__(256, 1)
fused_attn(const bf16* __restrict__ Qh, const bf16* __restrict__ Ql,
           const bf16* __restrict__ Kh, const bf16* __restrict__ Kl,
           const bf16* __restrict__ Vth, const bf16* __restrict__ Vtl,
           const float* __restrict__ mask,
           bf16* __restrict__ Oh, bf16* __restrict__ Ol)
{
    extern __shared__ __align__(128) char sm[];
    const uint32_t sb = smem_to_u32(sm);
    const int t = threadIdx.x, lane = t & 31, wid = t >> 5;
    const int wm = wid >> 2, wn = wid & 3;
    const int group = lane >> 2, tid4 = lane & 3;
    const int qt = blockIdx.x, win = blockIdx.y;
    float* red = (float*)(sm + FA_RED);

    {
        const long long qbase = (long long)win * 1024 + qt * 64;
        #pragma unroll
        for (int i = 0; i < 8; i++) {
            const int idx = t + i * 256;
            const int r = idx >> 5, c16 = idx & 31;
            const uint32_t d = sb + FA_QH + r * 528 + c16 * 16;
            const long long g = (qbase + r) * 256 + c16 * 8;
            cpasync16(d, Qh + g);
            cpasync16(d + (FA_QL - FA_QH), Ql + g);
        }
        cpcommit();
    }

    const uint32_t aQ  = sb + FA_QH + (uint32_t)((wm * 32 + (lane & 7) + ((lane >> 3) & 1) * 8) * 528
                                                 + ((lane >> 4) & 1) * 16);
    const uint32_t aQl = aQ + (FA_QL - FA_QH);
    const uint32_t bKr = (uint32_t)((wn * 32 + (lane & 7) + ((lane >> 4) & 1) * 8) * 80
                                    + ((lane >> 3) & 1) * 16);
    const uint32_t bVr = (uint32_t)((wn * 64 + (lane & 7) + ((lane >> 4) & 1) * 8) * 80
                                    + ((lane >> 3) & 1) * 16);
    const uint32_t aP  = sb + FA_P + (uint32_t)((wm * 32 + (lane & 7) + ((lane >> 3) & 1) * 8) * 272
                                                + ((lane >> 4) & 1) * 16);

    float acc_o[2][8][4];
    #pragma unroll
    for (int mi = 0; mi < 2; mi++)
        #pragma unroll
        for (int nj = 0; nj < 8; nj++)
            #pragma unroll
            for (int e = 0; e < 4; e++) acc_o[mi][nj][e] = 0.0f;
    float m_p[2][2] = {{-1e30f, -1e30f}, {-1e30f, -1e30f}};
    float l_p[2][2] = {{0.0f, 0.0f}, {0.0f, 0.0f}};

    fa_load_k(sb, 0, Kh, Kl, win, 0, 0, t);

    for (int kt = 0; kt < 8; kt++) {
        float acc_s[2][4][4];
        #pragma unroll
        for (int mi = 0; mi < 2; mi++)
            #pragma unroll
            for (int ni = 0; ni < 4; ni++)
                #pragma unroll
                for (int e = 0; e < 4; e++) acc_s[mi][ni][e] = 0.0f;

        for (int dc = 0; dc < 8; dc++) {
            if (dc < 7) fa_load_k(sb, (dc + 1) & 1, Kh, Kl, win, kt, dc + 1, t);
            else        fa_load_v(sb, 0, Vth, Vtl, win, kt, 0, t);
            cpwait<1>();
            __syncthreads();
            const uint32_t kb = sb + FA_K + (uint32_t)((dc & 1) * 20480);
            #pragma unroll
            for (int kk = 0; kk < 2; kk++) {
                uint32_t qhf[2][4], qlf[2][4], khf[2][4], klf[2][4];
                #pragma unroll
                for (int mi = 0; mi < 2; mi++) {
                    ldsm4(qhf[mi], aQ  + mi * (16 * 528) + dc * 64 + kk * 32);
                    ldsm4(qlf[mi], aQl + mi * (16 * 528) + dc * 64 + kk * 32);
                }
                #pragma unroll
                for (int p = 0; p < 2; p++) {
                    ldsm4(khf[p], kb + bKr + p * (16 * 80) + kk * 32);
                    ldsm4(klf[p], kb + 10240 + bKr + p * (16 * 80) + kk * 32);
                }
                #pragma unroll
                for (int mi = 0; mi < 2; mi++)
                    #pragma unroll
                    for (int ni = 0; ni < 4; ni++) {
                        const uint32_t* fh = &khf[ni >> 1][(ni & 1) * 2];
                        const uint32_t* fl = &klf[ni >> 1][(ni & 1) * 2];
                        mma_bf16(acc_s[mi][ni], qhf[mi], fh);
                        mma_bf16(acc_s[mi][ni], qhf[mi], fl);
                        mma_bf16(acc_s[mi][ni], qlf[mi], fh);
                    }
            }
            __syncthreads();
        }

        const float* mrow = mask + (long long)(win & 15) * 1048576;
        #pragma unroll
        for (int mi = 0; mi < 2; mi++)
            #pragma unroll
            for (int ni = 0; ni < 4; ni++)
                #pragma unroll
                for (int rr = 0; rr < 2; rr++) {
                    const int rg = qt * 64 + wm * 32 + mi * 16 + rr * 8 + group;
                    const int cg = kt * 128 + wn * 32 + ni * 8 + tid4 * 2;
                    const float2 mv = *(const float2*)(mrow + (long long)rg * 1024 + cg);
                    acc_s[mi][ni][rr * 2 + 0] += mv.x;
                    acc_s[mi][ni][rr * 2 + 1] += mv.y;
                }
        #pragma unroll
        for (int mi = 0; mi < 2; mi++)
            #pragma unroll
            for (int rr = 0; rr < 2; rr++) {
                float v = -1e30f;
                #pragma unroll
                for (int ni = 0; ni < 4; ni++)
                    v = fmaxf(v, fmaxf(acc_s[mi][ni][rr * 2], acc_s[mi][ni][rr * 2 + 1]));
                v = fmaxf(v, __shfl_xor_sync(0xffffffffu, v, 1));
                v = fmaxf(v, __shfl_xor_sync(0xffffffffu, v, 2));
                if (tid4 == 0) red[wn * 64 + wm * 32 + mi * 16 + rr * 8 + group] = v;
            }
        __syncthreads();
        float scl[2][2], lsum[2][2] = {{0.0f, 0.0f}, {0.0f, 0.0f}};
        #pragma unroll
        for (int mi = 0; mi < 2; mi++)
            #pragma unroll
            for (int rr = 0; rr < 2; rr++) {
                const int r64 = wm * 32 + mi * 16 + rr * 8 + group;
                const float mt = fmaxf(fmaxf(red[r64], red[64 + r64]),
                                       fmaxf(red[128 + r64], red[192 + r64]));
                const float mn = fmaxf(m_p[mi][rr], mt);
                scl[mi][rr] = __expf(m_p[mi][rr] - mn);
                m_p[mi][rr] = mn;
            }
        #pragma unroll
        for (int mi = 0; mi < 2; mi++)
            #pragma unroll
            for (int ni = 0; ni < 4; ni++)
                #pragma unroll
                for (int rr = 0; rr < 2; rr++) {
                    const float p0 = __expf(acc_s[mi][ni][rr * 2]     - m_p[mi][rr]);
                    const float p1 = __expf(acc_s[mi][ni][rr * 2 + 1] - m_p[mi][rr]);
                    lsum[mi][rr] += p0 + p1;
                    bf16 h0, l0, h1, l1;
                    split_bf16(p0, h0, l0);
                    split_bf16(p1, h1, l1);
                    const int r64 = wm * 32 + mi * 16 + rr * 8 + group;
                    const int cb = (wn * 32 + ni * 8 + tid4 * 2) * 2;
                    __nv_bfloat162 hh; hh.x = h0; hh.y = h1;
                    __nv_bfloat162 ll; ll.x = l0; ll.y = l1;
                    *(__nv_bfloat162*)(sm + FA_P + r64 * 272 + cb)         = hh;
                    *(__nv_bfloat162*)(sm + FA_P + 17408 + r64 * 272 + cb) = ll;
                }
        #pragma unroll
        for (int mi = 0; mi < 2; mi++)
            #pragma unroll
            for (int rr = 0; rr < 2; rr++)
                l_p[mi][rr] = l_p[mi][rr] * scl[mi][rr] + lsum[mi][rr];
        #pragma unroll
        for (int mi = 0; mi < 2; mi++)
            #pragma unroll
            for (int nj = 0; nj < 8; nj++)
                #pragma unroll
                for (int e = 0; e < 4; e++)
                    acc_o[mi][nj][e] *= scl[mi][e >> 1];

        for (int vc = 0; vc < 4; vc++) {
            if (vc < 3)      fa_load_v(sb, (vc + 1) & 1, Vth, Vtl, win, kt, vc + 1, t);
            else if (kt < 7) fa_load_k(sb, 0, Kh, Kl, win, kt + 1, 0, t);
            if (vc == 3 && kt == 7) { cpwait<0>(); } else { cpwait<1>(); }
            __syncthreads();
            const uint32_t vb = sb + FA_V + (uint32_t)((vc & 1) * 40960);
            #pragma unroll
            for (int kk = 0; kk < 2; kk++) {
                uint32_t phf[2][4], plf[2][4], vhf[4][4], vlf[4][4];
                #pragma unroll
                for (int mi = 0; mi < 2; mi++) {
                    ldsm4(phf[mi], aP + mi * (16 * 272) + vc * 64 + kk * 32);
                    ldsm4(plf[mi], aP + 17408 + mi * (16 * 272) + vc * 64 + kk * 32);
                }
                #pragma unroll
                for (int p = 0; p < 4; p++) {
                    ldsm4(vhf[p], vb + bVr + p * (16 * 80) + kk * 32);
                    ldsm4(vlf[p], vb + 20480 + bVr + p * (16 * 80) + kk * 32);
                }
                #pragma unroll
                for (int mi = 0; mi < 2; mi++)
                    #pragma unroll
                    for (int nj = 0; nj < 8; nj++) {
                        const uint32_t* fh = &vhf[nj >> 1][(nj & 1) * 2];
                        const uint32_t* fl = &vlf[nj >> 1][(nj & 1) * 2];
                        mma_bf16(acc_o[mi][nj], phf[mi], fh);
                        mma_bf16(acc_o[mi][nj], phf[mi], fl);
                        mma_bf16(acc_o[mi][nj], plf[mi], fh);
                    }
            }
            __syncthreads();
        }
    }

    #pragma unroll
    for (int mi = 0; mi < 2; mi++)
        #pragma unroll
        for (int rr = 0; rr < 2; rr++) {
            float v = l_p[mi][rr];
            v += __shfl_xor_sync(0xffffffffu, v, 1);
            v += __shfl_xor_sync(0xffffffffu, v, 2);
            if (tid4 == 0) red[wn * 64 + wm * 32 + mi * 16 + rr * 8 + group] = v;
        }
    __syncthreads();
    float inv[2][2];
    #pragma unroll
    for (int mi = 0; mi < 2; mi++)
        #pragma unroll
        for (int rr = 0; rr < 2; rr++) {
            const int r64 = wm * 32 + mi * 16 + rr * 8 + group;
            inv[mi][rr] = 1.0f / (red[r64] + red[64 + r64] + red[128 + r64] + red[192 + r64]);
        }
    const long long obase = (long long)win * 1024 + qt * 64;
    #pragma unroll
    for (int mi = 0; mi < 2; mi++)
        #pragma unroll
        for (int nj = 0; nj < 8; nj++) {
            const int r0 = wm * 32 + mi * 16 + group;
            const int c0 = wn * 64 + nj * 8 + tid4 * 2;
            #pragma unroll
            for (int rr = 0; rr < 2; rr++) {
                const float f0 = acc_o[mi][nj][rr * 2]     * inv[mi][rr];
                const float f1 = acc_o[mi][nj][rr * 2 + 1] * inv[mi][rr];
                bf16 h0, l0, h1, l1;
                split_bf16(f0, h0, l0);
                split_bf16(f1, h1, l1);
                const long long o = (obase + r0 + rr * 8) * 256 + c0;
                __nv_bfloat162 hh; hh.x = h0; hh.y = h1;
                __nv_bfloat162 ll; ll.x = l0; ll.y = l1;
                *(__nv_bfloat162*)(Oh + o) = hh;
                *(__nv_bfloat162*)(Ol + o) = ll;
            }
        }
}

// ===================== elementwise kernels ==================================
__global__ void __launch_bounds__(256)
prep_src(const float* __restrict__ src, bf16* swh, bf16* swl) {
    const int r = blockIdx.x, c = threadIdx.x;
    bf16 h, l;
    split_bf16(src[(long long)gather_win(r) * 256 + c], h, l);
    swh[(long long)r * 256 + c] = h; swl[(long long)r * 256 + c] = l;
}
__global__ void __launch_bounds__(256)
prep_tgt(const float* __restrict__ tgt, bf16* twh, bf16* twl) {
    const int r = blockIdx.x, c = threadIdx.x;
    bf16 h, l;
    split_bf16(tgt[(long long)gather_win(r) * 256 + c], h, l);
    twh[(long long)r * 256 + c] = h; twl[(long long)r * 256 + c] = l;
}
__global__ void __launch_bounds__(256)
wtrans(const float* __restrict__ W, bf16* Th, bf16* Tl, int K, int N) {
    const int idx = blockIdx.x * 256 + threadIdx.x;
    if (idx >= N * K) return;
    const int n = idx / K, k = idx - n * K;
    bf16 h, l;
    split_bf16(W[(long long)k * N + n], h, l);
    Th[idx] = h; Tl[idx] = l;
}
__global__ void __launch_bounds__(256)
wtransf(const float* __restrict__ W, float* __restrict__ T, int K, int N) {
    const int idx = blockIdx.x * 256 + threadIdx.x;
    if (idx >= N * K) return;
    const int n = idx / K, k = idx - n * K;
    T[idx] = W[(long long)k * N + n];
}
// per-row 2-slice int8 quantization
template<int K>
__global__ void __launch_bounds__(256)
quant_rows(const float* __restrict__ X, int8_t* __restrict__ Q1,
           int8_t* __restrict__ Q2, float* __restrict__ S) {
    const long long row = blockIdx.x;
    const int t = threadIdx.x;
    constexpr int PER = K / 256;
    float x[PER];
    float m = 0.0f;
    #pragma unroll
    for (int i = 0; i < PER; i++) {
        x[i] = X[row * K + i * 256 + t];
        m = fmaxf(m, fabsf(x[i]));
    }
    #pragma unroll
    for (int o = 16; o > 0; o >>= 1) m = fmaxf(m, __shfl_xor_sync(0xffffffffu, m, o));
    __shared__ float red[8];
    if ((t & 31) == 0) red[t >> 5] = m;
    __syncthreads();
    m = red[0];
    #pragma unroll
    for (int i = 1; i < 8; i++) m = fmaxf(m, red[i]);
    m = fmaxf(m, 1e-20f);
    const float invs = 127.0f / m;
    if (t == 0) S[row] = m * (1.0f / 127.0f);
    #pragma unroll
    for (int i = 0; i < PER; i++) {
        const float ap = x[i] * invs;
        const float q1 = rintf(ap);
        const float q2 = rintf((ap - q1) * 128.0f);
        Q1[row * K + i * 256 + t] = (int8_t)(int)q1;
        Q2[row * K + i * 256 + t] = (int8_t)(int)q2;
    }
}
// hcat = [source | msgln] quantized per row (K=512)
__global__ void __launch_bounds__(256)
quant_hcat(const float* __restrict__ src, const float* __restrict__ msgln,
           int8_t* __restrict__ Q1, int8_t* __restrict__ Q2, float* __restrict__ S) {
    const long long row = blockIdx.x;
    const int t = threadIdx.x;
    const float x0 = src[row * 256 + t];
    const float x1 = msgln[row * 256 + t];
    float m = fmaxf(fabsf(x0), fabsf(x1));
    #pragma unroll
    for (int o = 16; o > 0; o >>= 1) m = fmaxf(m, __shfl_xor_sync(0xffffffffu, m, o));
    __shared__ float red[8];
    if ((t & 31) == 0) red[t >> 5] = m;
    __syncthreads();
    m = red[0];
    #pragma unroll
    for (int i = 1; i < 8; i++) m = fmaxf(m, red[i]);
    m = fmaxf(m, 1e-20f);
    const float invs = 127.0f / m;
    if (t == 0) S[row] = m * (1.0f / 127.0f);
    {
        const float ap = x0 * invs;
        const float q1 = rintf(ap);
        const float q2 = rintf((ap - q1) * 128.0f);
        Q1[row * 512 + t] = (int8_t)(int)q1;
        Q2[row * 512 + t] = (int8_t)(int)q2;
    }
    {
        const float ap = x1 * invs;
        const float q1 = rintf(ap);
        const float q2 = rintf((ap - q1) * 128.0f);
        Q1[row * 512 + 256 + t] = (int8_t)(int)q1;
        Q2[row * 512 + 256 + t] = (int8_t)(int)q2;
    }
}
// LN1 (window order input) -> msgln fp32 in TOKEN order
__global__ void __launch_bounds__(256)
ln_msg(const float* __restrict__ X, const float* __restrict__ gamma,
       const float* __restrict__ beta, float* __restrict__ Y) {
    const long long row = blockIdx.x;
    const int t = threadIdx.x;
    const float x = X[row * 256 + t];
    float s = x, q = x * x;
    #pragma unroll
    for (int o = 16; o > 0; o >>= 1) {
        s += __shfl_xor_sync(0xffffffffu, s, o);
        q += __shfl_xor_sync(0xffffffffu, q, o);
    }
    __shared__ float ss[8], qq[8];
    const int w = t >> 5;
    if ((t & 31) == 0) { ss[w] = s; qq[w] = q; }
    __syncthreads();
    s = 0.0f; q = 0.0f;
    #pragma unroll
    for (int i = 0; i < 8; i++) { s += ss[i]; q += qq[i]; }
    const float mean = s * (1.0f / 256.0f);
    const float var  = q * (1.0f / 256.0f) - mean * mean;
    const float y = (x - mean) * rsqrtf(var + 1e-5f) * gamma[t] + beta[t];
    Y[(long long)gather_win((int)row) * 256 + t] = y;
}
__global__ void __launch_bounds__(256)
ln_res(const float* __restrict__ X, const float* __restrict__ gamma,
       const float* __restrict__ beta, const float* __restrict__ resid,
       float* __restrict__ out) {
    const long long row = blockIdx.x;
    const int t = threadIdx.x;
    const float x = X[row * 256 + t];
    float s = x, q = x * x;
    #pragma unroll
    for (int o = 16; o > 0; o >>= 1) {
        s += __shfl_xor_sync(0xffffffffu, s, o);
        q += __shfl_xor_sync(0xffffffffu, q, o);
    }
    __shared__ float ss[8], qq[8];
    const int w = t >> 5;
    if ((t & 31) == 0) { ss[w] = s; qq[w] = q; }
    __syncthreads();
    s = 0.0f; q = 0.0f;
    #pragma unroll
    for (int i = 0; i < 8; i++) { s += ss[i]; q += qq[i]; }
    const float mean = s * (1.0f / 256.0f);
    const float var  = q * (1.0f / 256.0f) - mean * mean;
    const float y = (x - mean) * rsqrtf(var + 1e-5f) * gamma[t] + beta[t];
    out[row * 256 + t] = y + resid[row * 256 + t];
}

// ===================== launch ===============================================
extern "C" void kernel_launch(void* const* d_in, const int* in_sizes, int n_in,
                              void* d_out, int out_size)
{
    const float* source = (const float*)d_in[0];
    const float* target = (const float*)d_in[1];
    const float* mask   = (const float*)d_in[2];
    const float* Wq     = (const float*)d_in[3];
    const float* Wk     = (const float*)d_in[4];
    const float* Wv     = (const float*)d_in[5];
    const float* Wmerge = (const float*)d_in[6];
    const float* gamma1 = (const float*)d_in[7];
    const float* beta1  = (const float*)d_in[8];
    const float* W1     = (const float*)d_in[9];
    const float* W2     = (const float*)d_in[10];
    const float* gamma2 = (const float*)d_in[11];
    const float* beta2  = (const float*)d_in[12];
    float* out = (float*)d_out;

    bf16 *swh, *swl, *twh, *twl, *qh, *ql, *kh, *kl, *vth, *vtl, *ah, *al;
    bf16 *wqh, *wql, *wkvh, *wkvl, *wmh, *wml;
    float *msg, *msgln, *hidf, *msg2, *w1tf, *w2tf;
    int8_t *hc1, *hc2, *hd1, *hd2, *w1q1, *w1q2, *w2q1, *w2q2;
    float *sahc, *sahd, *sbw1, *sbw2;
    cudaGetSymbolAddress((void**)&swh, g_swh); cudaGetSymbolAddress((void**)&swl, g_swl);
    cudaGetSymbolAddress((void**)&twh, g_twh); cudaGetSymbolAddress((void**)&twl, g_twl);
    cudaGetSymbolAddress((void**)&qh,  g_qh);  cudaGetSymbolAddress((void**)&ql,  g_ql);
    cudaGetSymbolAddress((void**)&kh,  g_kh);  cudaGetSymbolAddress((void**)&kl,  g_kl);
    cudaGetSymbolAddress((void**)&vth, g_vth); cudaGetSymbolAddress((void**)&vtl, g_vtl);
    cudaGetSymbolAddress((void**)&ah,  g_ah);  cudaGetSymbolAddress((void**)&al,  g_al);
    cudaGetSymbolAddress((void**)&msg, g_msg); cudaGetSymbolAddress((void**)&msgln, g_msgln);
    cudaGetSymbolAddress((void**)&hidf, g_hidf); cudaGetSymbolAddress((void**)&msg2, g_msg2);
    cudaGetSymbolAddress((void**)&wqh, g_wqh); cudaGetSymbolAddress((void**)&wql, g_wql);
    cudaGetSymbolAddress((void**)&wkvh, g_wkvh); cudaGetSymbolAddress((void**)&wkvl, g_wkvl);
    cudaGetSymbolAddress((void**)&wmh, g_wmh); cudaGetSymbolAddress((void**)&wml, g_wml);
    cudaGetSymbolAddress((void**)&w1tf, g_w1tf); cudaGetSymbolAddress((void**)&w2tf, g_w2tf);
    cudaGetSymbolAddress((void**)&hc1, g_hc1); cudaGetSymbolAddress((void**)&hc2, g_hc2);
    cudaGetSymbolAddress((void**)&hd1, g_hd1); cudaGetSymbolAddress((void**)&hd2, g_hd2);
    cudaGetSymbolAddress((void**)&w1q1, g_w1q1); cudaGetSymbolAddress((void**)&w1q2, g_w1q2);
    cudaGetSymbolAddress((void**)&w2q1, g_w2q1); cudaGetSymbolAddress((void**)&w2q2, g_w2q2);
    cudaGetSymbolAddress((void**)&sahc, g_sahc); cudaGetSymbolAddress((void**)&sahd, g_sahd);
    cudaGetSymbolAddress((void**)&sbw1, g_sbw1); cudaGetSymbolAddress((void**)&sbw2, g_sbw2);

    cudaFuncSetAttribute(gemm_mma<0>, cudaFuncAttributeMaxDynamicSharedMemorySize, SMEM_BYTES);
    cudaFuncSetAttribute(gemm_mma<5>, cudaFuncAttributeMaxDynamicSharedMemorySize, SMEM_BYTES);
    cudaFuncSetAttribute(gemm_mma<6>, cudaFuncAttributeMaxDynamicSharedMemorySize, SMEM_BYTES);
    cudaFuncSetAttribute(gemm_i8<0>,  cudaFuncAttributeMaxDynamicSharedMemorySize, SMEM_BYTES);
    cudaFuncSetAttribute(gemm_i8<1>,  cudaFuncAttributeMaxDynamicSharedMemorySize, SMEM_BYTES);
    cudaFuncSetAttribute(fused_attn,  cudaFuncAttributeMaxDynamicSharedMemorySize, FA_SMEM);

    // conversions / weight prep
    prep_src<<<TOK, 256>>>(source, swh, swl);
    prep_tgt<<<TOK, 256>>>(target, twh, twl);
    wtrans<<<(D * D + 255) / 256, 256>>>(Wq, wqh, wql, D, D);
    wtrans<<<(D * D + 255) / 256, 256>>>(Wk, wkvh, wkvl, D, D);
    wtrans<<<(D * D + 255) / 256, 256>>>(Wv, wkvh + 256 * 256, wkvl + 256 * 256, D, D);
    wtrans<<<(D * D + 255) / 256, 256>>>(Wmerge, wmh, wml, D, D);
    wtransf<<<(HID * 512 + 255) / 256, 256>>>(W1, w1tf, 512, HID);
    wtransf<<<(D * HID + 255) / 256, 256>>>(W2, w2tf, HID, D);
    quant_rows<512><<<HID, 256>>>(w1tf, w1q1, w1q2, sbw1);
    quant_rows<2048><<<D, 256>>>(w2tf, w2q1, w2q2, sbw2);

    // Q projection (scaled 1/16, hi/lo); K+V^T combined projection
    gemm_mma<5><<<dim3(2, 256, 1), 256, SMEM_BYTES>>>(swh, swl, wqh, wql,
        nullptr, qh, ql, TOK, D, D, 0, 0, 0);
    gemm_mma<6><<<dim3(4, 256, 1), 256, SMEM_BYTES>>>(twh, twl, wkvh, wkvl,
        nullptr, kh, kl, TOK, 512, D, 0, 0, 0);

    // fused attention
    fused_attn<<<dim3(16, 32), 256, FA_SMEM>>>(qh, ql, kh, kl, vth, vtl, mask, ah, al);

    // merge projection -> msg fp32 (window order)
    gemm_mma<0><<<dim3(2, 256, 1), 256, SMEM_BYTES>>>(ah, al, wmh, wml,
        msg, nullptr, nullptr, TOK, D, D, 0, 0, 0);
    // LN1 -> msgln fp32 (token order)
    ln_msg<<<TOK, 256>>>(msg, gamma1, beta1, msgln);
    // quantize hcat = [source | msgln]
    quant_hcat<<<TOK, 256>>>(source, msgln, hc1, hc2, sahc);
    // MLP1 int8 (scale + GELU -> fp32 hidden)
    gemm_i8<1><<<dim3(16, 256, 1), 256, SMEM_BYTES>>>(hc1, hc2, w1q1, w1q2,
        sahc, sbw1, hidf, TOK, HID, 512);
    // quantize hidden
    quant_rows<2048><<<TOK, 256>>>(hidf, hd1, hd2, sahd);
    // MLP2 int8 -> msg2 fp32
    gemm_i8<0><<<dim3(2, 256, 1), 256, SMEM_BYTES>>>(hd1, hd2, w2q1, w2q2,
        sahd, sbw2, msg2, TOK, D, HID);
    // LN2 + residual
    ln_res<<<TOK, 256>>>(msg2, gamma2, beta2, source, out);
}

// round 9
// speedup vs baseline: 1.9147x; 1.9147x over previous
#include <cuda_runtime.h>
#include <cuda_bf16.h>
#include <math.h>
#include <stdint.h>

#define DI __device__ __forceinline__

// Fixed problem shapes (b=2, h=w=128, d=256, ns=4, f=4)
static constexpr int TOK  = 32768;
static constexpr int D    = 256;
static constexpr int L    = 1024;
static constexpr int NWIN = 32;
static constexpr int HID  = 2048;

typedef __nv_bfloat16 bf16;

// ===================== PTX helpers (base sm_103 legal: sm_80 era) ===========
DI uint32_t smem_to_u32(const void* p) {
    uint32_t a;
    asm("{ .reg .u64 t; cvta.to.shared.u64 t, %1; cvt.u32.u64 %0, t; }"
        : "=r"(a) : "l"(p));
    return a;
}
DI void ldsm4(uint32_t* r, uint32_t addr) {
    asm volatile("ldmatrix.sync.aligned.m8n8.x4.shared.b16 {%0,%1,%2,%3}, [%4];"
                 : "=r"(r[0]), "=r"(r[1]), "=r"(r[2]), "=r"(r[3]) : "r"(addr));
}
DI void mma_bf16(float* d, const uint32_t* a, const uint32_t* b) {
    asm volatile("mma.sync.aligned.m16n8k16.row.col.f32.bf16.bf16.f32 "
                 "{%0,%1,%2,%3}, {%4,%5,%6,%7}, {%8,%9}, {%0,%1,%2,%3};"
                 : "+f"(d[0]), "+f"(d[1]), "+f"(d[2]), "+f"(d[3])
                 : "r"(a[0]), "r"(a[1]), "r"(a[2]), "r"(a[3]), "r"(b[0]), "r"(b[1]));
}
DI void cpasync16(uint32_t dst, const void* src) {
    asm volatile("cp.async.cg.shared.global [%0], [%1], 16;" :: "r"(dst), "l"(src));
}
DI void cpcommit() { asm volatile("cp.async.commit_group;" ::: "memory"); }
template<int N> DI void cpwait() { asm volatile("cp.async.wait_group %0;" :: "n"(N) : "memory"); }

// ===================== index math + misc ====================================
DI int gather_win(int r) {
    int w = r >> 10, p = r & 1023;
    int b = w >> 4, wi = (w >> 2) & 3, wj = w & 3;
    int rr = p >> 5, cc = p & 31;
    int i = (wi * 32 + rr + 16) & 127;
    int j = (wj * 32 + cc + 16) & 127;
    return (b << 14) + (i << 7) + j;
}
DI float gelu_exact(float x) { return 0.5f * x * (1.0f + erff(x * 0.70710678118654752f)); }
DI void split_bf16(float x, bf16& h, bf16& l) {
    h = __float2bfloat16(x);
    l = __float2bfloat16(x - __bfloat162float(h));
}

// ===================== device scratch (no allocations) ======================
__device__ __align__(16) bf16 g_swh[TOK * D],  g_swl[TOK * D];     // source, window order
__device__ __align__(16) bf16 g_twh[TOK * D],  g_twl[TOK * D];     // target, window order
__device__ __align__(16) bf16 g_qh[TOK * D],   g_ql[TOK * D];      // Q/16, window order
__device__ __align__(16) bf16 g_kh[TOK * D],   g_kl[TOK * D];
__device__ __align__(16) bf16 g_vth[TOK * D],  g_vtl[TOK * D];     // V^T per window [win][256][1024]
__device__ __align__(16) bf16 g_ah[TOK * D],   g_al[TOK * D];      // attn out (window order)
__device__ float g_msg[TOK * D];
__device__ __align__(16) bf16 g_hch[TOK * 512], g_hcl[TOK * 512];  // hcat [TOK,512] token order
__device__ __align__(16) bf16 g_hih[(size_t)TOK * HID], g_hil[(size_t)TOK * HID];
__device__ float g_msg2[TOK * D];
__device__ __align__(16) bf16 g_wqh[D * D], g_wql[D * D];
__device__ __align__(16) bf16 g_wkvh[512 * D], g_wkvl[512 * D];    // [Wk^T ; Wv^T]
__device__ __align__(16) bf16 g_wmh[D * D], g_wml[D * D];
__device__ __align__(16) bf16 g_w1h[HID * 512], g_w1l[HID * 512];  // W1^T [2048,512]
__device__ __align__(16) bf16 g_w2h[D * HID],   g_w2l[D * HID];    // W2^T [256,2048]

// ===================== HMMA GEMM ============================================
// NT GEMM: C[M,N] = A[M,K] @ B[N,K]^T, bf16 hi/lo 3-pass split, fp32 accum.
// CTA tile 128x128, 8 warps (2Mx4N), warp tile 64x32, K-chunk 32, double buffer.
static constexpr int TILE_B  = 10240;   // 128 rows * 80B (padded stride, conflict-free)
static constexpr int STAGE_B = 4 * TILE_B;
static constexpr int SMEM_BYTES = 2 * STAGE_B;  // 81920

DI void stage_load(uint32_t sdst,
                   const bf16* __restrict__ Ah, const bf16* __restrict__ Al,
                   const bf16* __restrict__ Bh, const bf16* __restrict__ Bl,
                   int arow, int brow, int K, int k0, int t) {
    #pragma unroll
    for (int h = 0; h < 2; h++) {
        const int idx = t + h * 256;
        const int r = idx >> 2, c = (idx & 3) << 3;   // c in bf16 elements
        const uint32_t so = sdst + r * 80 + c * 2;
        const long long ga = (long long)(arow + r) * K + k0 + c;
        const long long gb = (long long)(brow + r) * K + k0 + c;
        cpasync16(so,              Ah + ga);
        cpasync16(so + TILE_B,     Al + ga);
        cpasync16(so + 2 * TILE_B, Bh + gb);
        cpasync16(so + 3 * TILE_B, Bl + gb);
    }
}

// EPI: 0=fp32, 3=gelu->bf16 hi/lo, 5=bf16 hi/lo scaled 1/16 (Q),
//      6=combined K (cols<256, hi/lo ld=256) | V^T per-window (cols>=256)
template<int EPI>
__global__ void __launch_bounds__(256, 2)
gemm_mma(const bf16* __restrict__ Ahi, const bf16* __restrict__ Alo,
         const bf16* __restrict__ Bhi, const bf16* __restrict__ Blo,
         float* __restrict__ Cf, bf16* __restrict__ Chi, bf16* __restrict__ Clo,
         int M, int N, int K, long long sA, long long sB, long long sC)
{
    extern __shared__ __align__(128) char sm[];
    const uint32_t sb = smem_to_u32(sm);
    const int t = threadIdx.x, lane = t & 31, wid = t >> 5;
    const int wm = wid >> 2, wn = wid & 3;          // 2 x 4 warp grid
    const int bn = blockIdx.x, bm = blockIdx.y, bz = blockIdx.z;
    Ahi += (long long)bz * sA; Alo += (long long)bz * sA;
    Bhi += (long long)bz * sB; Blo += (long long)bz * sB;
    const int arow = bm * 128, brow = bn * 128;

    const uint32_t aoff = (uint32_t)((wm * 64 + (lane & 7) + ((lane >> 3) & 1) * 8) * 80
                                     + (((lane >> 4) & 1) * 8) * 2);
    const uint32_t boff = (uint32_t)((wn * 32 + (lane & 7) + ((lane >> 4) & 1) * 8) * 80
                                     + (((lane >> 3) & 1) * 8) * 2);

    float acc[4][4][4];
    #pragma unroll
    for (int i = 0; i < 4; i++)
        #pragma unroll
        for (int j = 0; j < 4; j++)
            #pragma unroll
            for (int e = 0; e < 4; e++) acc[i][j][e] = 0.0f;

    const int NC = K >> 5;
    stage_load(sb, Ahi, Alo, Bhi, Blo, arow, brow, K, 0, t);
    cpcommit();

    for (int c = 0; c < NC; c++) {
        const uint32_t cur = sb + (uint32_t)(c & 1) * STAGE_B;
        if (c + 1 < NC) {
            stage_load(sb + (uint32_t)((c + 1) & 1) * STAGE_B,
                       Ahi, Alo, Bhi, Blo, arow, brow, K, (c + 1) << 5, t);
            cpcommit();
            cpwait<1>();
        } else {
            cpwait<0>();
        }
        __syncthreads();

        #pragma unroll
        for (int k16 = 0; k16 < 2; k16++) {
            uint32_t ah[4][4], al[4][4], bh[2][4], bl[2][4];
            #pragma unroll
            for (int mi = 0; mi < 4; mi++) {
                ldsm4(ah[mi], cur + aoff + mi * (16 * 80) + k16 * 32);
                ldsm4(al[mi], cur + TILE_B + aoff + mi * (16 * 80) + k16 * 32);
            }
            #pragma unroll
            for (int p = 0; p < 2; p++) {
                ldsm4(bh[p], cur + 2 * TILE_B + boff + p * (16 * 80) + k16 * 32);
                ldsm4(bl[p], cur + 3 * TILE_B + boff + p * (16 * 80) + k16 * 32);
            }
            #pragma unroll
            for (int mi = 0; mi < 4; mi++)
                #pragma unroll
                for (int ni = 0; ni < 4; ni++) {
                    const uint32_t* fh = &bh[ni >> 1][(ni & 1) * 2];
                    const uint32_t* fl = &bl[ni >> 1][(ni & 1) * 2];
                    mma_bf16(acc[mi][ni], ah[mi], fh);
                    mma_bf16(acc[mi][ni], ah[mi], fl);
                    mma_bf16(acc[mi][ni], al[mi], fh);
                }
        }
        __syncthreads();
    }

    const int group = lane >> 2, tid4 = lane & 3;
    #pragma unroll
    for (int mi = 0; mi < 4; mi++) {
        #pragma unroll
        for (int ni = 0; ni < 4; ni++) {
            const int r0 = bm * 128 + wm * 64 + mi * 16 + group;
            const int c0 = bn * 128 + wn * 32 + ni * 8 + tid4 * 2;
            const float* d = acc[mi][ni];
            if (EPI == 0) {
                float* Cp = Cf + (long long)bz * sC;
                *(float2*)(Cp + (long long)r0 * N + c0)       = make_float2(d[0], d[1]);
                *(float2*)(Cp + (long long)(r0 + 8) * N + c0) = make_float2(d[2], d[3]);
            } else if (EPI == 3 || EPI == 5) {
                #pragma unroll
                for (int rr = 0; rr < 2; rr++) {
                    float f0 = d[rr * 2], f1 = d[rr * 2 + 1];
                    if (EPI == 3) { f0 = gelu_exact(f0); f1 = gelu_exact(f1); }
                    if (EPI == 5) { f0 *= 0.0625f; f1 *= 0.0625f; }
                    bf16 h0, l0, h1, l1;
                    split_bf16(f0, h0, l0);
                    split_bf16(f1, h1, l1);
                    const long long base = (long long)bz * sC + (long long)(r0 + rr * 8) * N + c0;
                    __nv_bfloat162 hh; hh.x = h0; hh.y = h1;
                    __nv_bfloat162 ll; ll.x = l0; ll.y = l1;
                    *(__nv_bfloat162*)(Chi + base) = hh;
                    *(__nv_bfloat162*)(Clo + base) = ll;
                }
            } else { // EPI == 6
                if (c0 < 256) {
                    #pragma unroll
                    for (int rr = 0; rr < 2; rr++) {
                        bf16 h0, l0, h1, l1;
                        split_bf16(d[rr * 2], h0, l0);
                        split_bf16(d[rr * 2 + 1], h1, l1);
                        const long long base = (long long)(r0 + rr * 8) * 256 + c0;
                        __nv_bfloat162 hh; hh.x = h0; hh.y = h1;
                        __nv_bfloat162 ll; ll.x = l0; ll.y = l1;
                        *(__nv_bfloat162*)(Chi + base) = hh;
                        *(__nv_bfloat162*)(Clo + base) = ll;
                    }
                } else {
                    #pragma unroll
                    for (int rr = 0; rr < 2; rr++) {
                        const int r = r0 + rr * 8;
                        const int win = r >> 10, ml = r & 1023;
                        #pragma unroll
                        for (int e = 0; e < 2; e++) {
                            bf16 hh, ll;
                            split_bf16(d[rr * 2 + e], hh, ll);
                            const long long o = (long long)win * 262144
                                              + (long long)(c0 - 256 + e) * 1024 + ml;
                            g_vth[o] = hh; g_vtl[o] = ll;
                        }
                    }
                }
            }
        }
    }
}

// ===================== fused flash attention ================================
// Grid (16 qtiles, 32 windows), 256 threads. Q tile 64 rows; K tiles of 128.
static constexpr int FA_QH   = 0;                 // 64 x 528
static constexpr int FA_QL   = 33792;             // 64 x 528
static constexpr int FA_K    = 67584;             // 2 stages x (hi 10240 + lo 10240)
static constexpr int FA_V    = 108544;            // 2 stages x (hi 20480 + lo 20480)
static constexpr int FA_P    = 190464;            // Ph 17408 + Pl 17408
static constexpr int FA_RED  = 225280;            // 4 x 64 floats
static constexpr int FA_SMEM = 226304;

DI void fa_load_k(uint32_t sb, int stage, const bf16* __restrict__ Kh,
                  const bf16* __restrict__ Kl, int win, int kt, int dc, int t) {
    const long long base = (long long)win * 1024 + kt * 128;
    const uint32_t d0 = sb + FA_K + (uint32_t)stage * 20480;
    #pragma unroll
    for (int i = 0; i < 2; i++) {
        const int idx = t + i * 256;
        const int r = idx >> 2, c16 = idx & 3;
        const long long g = (base + r) * 256 + dc * 32 + c16 * 8;
        cpasync16(d0 + r * 80 + c16 * 16,         Kh + g);
        cpasync16(d0 + 10240 + r * 80 + c16 * 16, Kl + g);
    }
    cpcommit();
}
DI void fa_load_v(uint32_t sb, int stage, const bf16* __restrict__ Vh,
                  const bf16* __restrict__ Vl, int win, int kt, int vc, int t) {
    const uint32_t d0 = sb + FA_V + (uint32_t)stage * 40960;
    const long long base = (long long)win * 262144;
    #pragma unroll
    for (int i = 0; i < 4; i++) {
        const int idx = t + i * 256;
        const int r = idx >> 2, c16 = idx & 3;
        const long long g = base + (long long)r * 1024 + kt * 128 + vc * 32 + c16 * 8;
        cpasync16(d0 + r * 80 + c16 * 16,         Vh + g);
        cpasync16(d0 + 20480 + r * 80 + c16 * 16, Vl + g);
    }
    cpcommit();
}

__global__ void __launch_bounds__(256, 1)
fused_attn(const bf16* __restrict__ Qh, const bf16* __restrict__ Ql,
           const bf16* __restrict__ Kh, const bf16* __restrict__ Kl,
           const bf16* __restrict__ Vth, const bf16* __restrict__ Vtl,
           const float* __restrict__ mask,
           bf16* __restrict__ Oh, bf16* __restrict__ Ol)
{
    extern __shared__ __align__(128) char sm[];
    const uint32_t sb = smem_to_u32(sm);
    const int t = threadIdx.x, lane = t & 31, wid = t >> 5;
    const int wm = wid >> 2, wn = wid & 3;
    const int group = lane >> 2, tid4 = lane & 3;
    const int qt = blockIdx.x, win = blockIdx.y;
    float* red = (float*)(sm + FA_RED);

    {
        const long long qbase = (long long)win * 1024 + qt * 64;
        #pragma unroll
        for (int i = 0; i < 8; i++) {
            const int idx = t + i * 256;
            const int r = idx >> 5, c16 = idx & 31;
            const uint32_t d = sb + FA_QH + r * 528 + c16 * 16;
            const long long g = (qbase + r) * 256 + c16 * 8;
            cpasync16(d, Qh + g);
            cpasync16(d + (FA_QL - FA_QH), Ql + g);
        }
        cpcommit();
    }

    const uint32_t aQ  = sb + FA_QH + (uint32_t)((wm * 32 + (lane & 7) + ((lane >> 3) & 1) * 8) * 528
                                                 + ((lane >> 4) & 1) * 16);
    const uint32_t aQl = aQ + (FA_QL - FA_QH);
    const uint32_t bKr = (uint32_t)((wn * 32 + (lane & 7) + ((lane >> 4) & 1) * 8) * 80
                                    + ((lane >> 3) & 1) * 16);
    const uint32_t bVr = (uint32_t)((wn * 64 + (lane & 7) + ((lane >> 4) & 1) * 8) * 80
                                    + ((lane >> 3) & 1) * 16);
    const uint32_t aP  = sb + FA_P + (uint32_t)((wm * 32 + (lane & 7) + ((lane >> 3) & 1) * 8) * 272
                                                + ((lane >> 4) & 1) * 16);

    float acc_o[2][8][4];
    #pragma unroll
    for (int mi = 0; mi < 2; mi++)
        #pragma unroll
        for (int nj = 0; nj < 8; nj++)
            #pragma unroll
            for (int e = 0; e < 4; e++) acc_o[mi][nj][e] = 0.0f;
    float m_p[2][2] = {{-1e30f, -1e30f}, {-1e30f, -1e30f}};
    float l_p[2][2] = {{0.0f, 0.0f}, {0.0f, 0.0f}};

    fa_load_k(sb, 0, Kh, Kl, win, 0, 0, t);

    for (int kt = 0; kt < 8; kt++) {
        float acc_s[2][4][4];
        #pragma unroll
        for (int mi = 0; mi < 2; mi++)
            #pragma unroll
            for (int ni = 0; ni < 4; ni++)
                #pragma unroll
                for (int e = 0; e < 4; e++) acc_s[mi][ni][e] = 0.0f;

        for (int dc = 0; dc < 8; dc++) {
            if (dc < 7) fa_load_k(sb, (dc + 1) & 1, Kh, Kl, win, kt, dc + 1, t);
            else        fa_load_v(sb, 0, Vth, Vtl, win, kt, 0, t);
            cpwait<1>();
            __syncthreads();
            const uint32_t kb = sb + FA_K + (uint32_t)((dc & 1) * 20480);
            #pragma unroll
            for (int kk = 0; kk < 2; kk++) {
                uint32_t qhf[2][4], qlf[2][4], khf[2][4], klf[2][4];
                #pragma unroll
                for (int mi = 0; mi < 2; mi++) {
                    ldsm4(qhf[mi], aQ  + mi * (16 * 528) + dc * 64 + kk * 32);
                    ldsm4(qlf[mi], aQl + mi * (16 * 528) + dc * 64 + kk * 32);
                }
                #pragma unroll
                for (int p = 0; p < 2; p++) {
                    ldsm4(khf[p], kb + bKr + p * (16 * 80) + kk * 32);
                    ldsm4(klf[p], kb + 10240 + bKr + p * (16 * 80) + kk * 32);
                }
                #pragma unroll
                for (int mi = 0; mi < 2; mi++)
                    #pragma unroll
                    for (int ni = 0; ni < 4; ni++) {
                        const uint32_t* fh = &khf[ni >> 1][(ni & 1) * 2];
                        const uint32_t* fl = &klf[ni >> 1][(ni & 1) * 2];
                        mma_bf16(acc_s[mi][ni], qhf[mi], fh);
                        mma_bf16(acc_s[mi][ni], qhf[mi], fl);
                        mma_bf16(acc_s[mi][ni], qlf[mi], fh);
                    }
            }
            __syncthreads();
        }

        const float* mrow = mask + (long long)(win & 15) * 1048576;
        #pragma unroll
        for (int mi = 0; mi < 2; mi++)
            #pragma unroll
            for (int ni = 0; ni < 4; ni++)
                #pragma unroll
                for (int rr = 0; rr < 2; rr++) {
                    const int rg = qt * 64 + wm * 32 + mi * 16 + rr * 8 + group;
                    const int cg = kt * 128 + wn * 32 + ni * 8 + tid4 * 2;
                    const float2 mv = *(const float2*)(mrow + (long long)rg * 1024 + cg);
                    acc_s[mi][ni][rr * 2 + 0] += mv.x;
                    acc_s[mi][ni][rr * 2 + 1] += mv.y;
                }
        #pragma unroll
        for (int mi = 0; mi < 2; mi++)
            #pragma unroll
            for (int rr = 0; rr < 2; rr++) {
                float v = -1e30f;
                #pragma unroll
                for (int ni = 0; ni < 4; ni++)
                    v = fmaxf(v, fmaxf(acc_s[mi][ni][rr * 2], acc_s[mi][ni][rr * 2 + 1]));
                v = fmaxf(v, __shfl_xor_sync(0xffffffffu, v, 1));
                v = fmaxf(v, __shfl_xor_sync(0xffffffffu, v, 2));
                if (tid4 == 0) red[wn * 64 + wm * 32 + mi * 16 + rr * 8 + group] = v;
            }
        __syncthreads();
        float scl[2][2], lsum[2][2] = {{0.0f, 0.0f}, {0.0f, 0.0f}};
        #pragma unroll
        for (int mi = 0; mi < 2; mi++)
            #pragma unroll
            for (int rr = 0; rr < 2; rr++) {
                const int r64 = wm * 32 + mi * 16 + rr * 8 + group;
                const float mt = fmaxf(fmaxf(red[r64], red[64 + r64]),
                                       fmaxf(red[128 + r64], red[192 + r64]));
                const float mn = fmaxf(m_p[mi][rr], mt);
                scl[mi][rr] = __expf(m_p[mi][rr] - mn);
                m_p[mi][rr] = mn;
            }
        #pragma unroll
        for (int mi = 0; mi < 2; mi++)
            #pragma unroll
            for (int ni = 0; ni < 4; ni++)
                #pragma unroll
                for (int rr = 0; rr < 2; rr++) {
                    const float p0 = __expf(acc_s[mi][ni][rr * 2]     - m_p[mi][rr]);
                    const float p1 = __expf(acc_s[mi][ni][rr * 2 + 1] - m_p[mi][rr]);
                    lsum[mi][rr] += p0 + p1;
                    bf16 h0, l0, h1, l1;
                    split_bf16(p0, h0, l0);
                    split_bf16(p1, h1, l1);
                    const int r64 = wm * 32 + mi * 16 + rr * 8 + group;
                    const int cb = (wn * 32 + ni * 8 + tid4 * 2) * 2;
                    __nv_bfloat162 hh; hh.x = h0; hh.y = h1;
                    __nv_bfloat162 ll; ll.x = l0; ll.y = l1;
                    *(__nv_bfloat162*)(sm + FA_P + r64 * 272 + cb)         = hh;
                    *(__nv_bfloat162*)(sm + FA_P + 17408 + r64 * 272 + cb) = ll;
                }
        #pragma unroll
        for (int mi = 0; mi < 2; mi++)
            #pragma unroll
            for (int rr = 0; rr < 2; rr++)
                l_p[mi][rr] = l_p[mi][rr] * scl[mi][rr] + lsum[mi][rr];
        #pragma unroll
        for (int mi = 0; mi < 2; mi++)
            #pragma unroll
            for (int nj = 0; nj < 8; nj++)
                #pragma unroll
                for (int e = 0; e < 4; e++)
                    acc_o[mi][nj][e] *= scl[mi][e >> 1];

        for (int vc = 0; vc < 4; vc++) {
            if (vc < 3)      fa_load_v(sb, (vc + 1) & 1, Vth, Vtl, win, kt, vc + 1, t);
            else if (kt < 7) fa_load_k(sb, 0, Kh, Kl, win, kt + 1, 0, t);
            if (vc == 3 && kt == 7) { cpwait<0>(); } else { cpwait<1>(); }
            __syncthreads();
            const uint32_t vb = sb + FA_V + (uint32_t)((vc & 1) * 40960);
            #pragma unroll
            for (int kk = 0; kk < 2; kk++) {
                uint32_t phf[2][4], plf[2][4], vhf[4][4], vlf[4][4];
                #pragma unroll
                for (int mi = 0; mi < 2; mi++) {
                    ldsm4(phf[mi], aP + mi * (16 * 272) + vc * 64 + kk * 32);
                    ldsm4(plf[mi], aP + 17408 + mi * (16 * 272) + vc * 64 + kk * 32);
                }
                #pragma unroll
                for (int p = 0; p < 4; p++) {
                    ldsm4(vhf[p], vb + bVr + p * (16 * 80) + kk * 32);
                    ldsm4(vlf[p], vb + 20480 + bVr + p * (16 * 80) + kk * 32);
                }
                #pragma unroll
                for (int mi = 0; mi < 2; mi++)
                    #pragma unroll
                    for (int nj = 0; nj < 8; nj++) {
                        const uint32_t* fh = &vhf[nj >> 1][(nj & 1) * 2];
                        const uint32_t* fl = &vlf[nj >> 1][(nj & 1) * 2];
                        mma_bf16(acc_o[mi][nj], phf[mi], fh);
                        mma_bf16(acc_o[mi][nj], phf[mi], fl);
                        mma_bf16(acc_o[mi][nj], plf[mi], fh);
                    }
            }
            __syncthreads();
        }
    }

    #pragma unroll
    for (int mi = 0; mi < 2; mi++)
        #pragma unroll
        for (int rr = 0; rr < 2; rr++) {
            float v = l_p[mi][rr];
            v += __shfl_xor_sync(0xffffffffu, v, 1);
            v += __shfl_xor_sync(0xffffffffu, v, 2);
            if (tid4 == 0) red[wn * 64 + wm * 32 + mi * 16 + rr * 8 + group] = v;
        }
    __syncthreads();
    float inv[2][2];
    #pragma unroll
    for (int mi = 0; mi < 2; mi++)
        #pragma unroll
        for (int rr = 0; rr < 2; rr++) {
            const int r64 = wm * 32 + mi * 16 + rr * 8 + group;
            inv[mi][rr] = 1.0f / (red[r64] + red[64 + r64] + red[128 + r64] + red[192 + r64]);
        }
    const long long obase = (long long)win * 1024 + qt * 64;
    #pragma unroll
    for (int mi = 0; mi < 2; mi++)
        #pragma unroll
        for (int nj = 0; nj < 8; nj++) {
            const int r0 = wm * 32 + mi * 16 + group;
            const int c0 = wn * 64 + nj * 8 + tid4 * 2;
            #pragma unroll
            for (int rr = 0; rr < 2; rr++) {
                const float f0 = acc_o[mi][nj][rr * 2]     * inv[mi][rr];
                const float f1 = acc_o[mi][nj][rr * 2 + 1] * inv[mi][rr];
                bf16 h0, l0, h1, l1;
                split_bf16(f0, h0, l0);
                split_bf16(f1, h1, l1);
                const long long o = (obase + r0 + rr * 8) * 256 + c0;
                __nv_bfloat162 hh; hh.x = h0; hh.y = h1;
                __nv_bfloat162 ll; ll.x = l0; ll.y = l1;
                *(__nv_bfloat162*)(Oh + o) = hh;
                *(__nv_bfloat162*)(Ol + o) = ll;
            }
        }
}

// ===================== elementwise kernels ==================================
// Combined source/target conversion: grid (TOK, 2). y=0: source (window + hcat),
// y=1: target (window order).
__global__ void __launch_bounds__(256)
prep_st(const float* __restrict__ src, const float* __restrict__ tgt,
        bf16* swh, bf16* swl, bf16* hch, bf16* hcl, bf16* twh, bf16* twl) {
    const int r = blockIdx.x, c = threadIdx.x;
    bf16 h, l;
    if (blockIdx.y == 0) {
        split_bf16(src[(long long)gather_win(r) * 256 + c], h, l);
        swh[(long long)r * 256 + c] = h; swl[(long long)r * 256 + c] = l;
        split_bf16(src[(long long)r * 256 + c], h, l);
        hch[(long long)r * 512 + c] = h; hcl[(long long)r * 512 + c] = l;
    } else {
        split_bf16(tgt[(long long)gather_win(r) * 256 + c], h, l);
        twh[(long long)r * 256 + c] = h; twl[(long long)r * 256 + c] = l;
    }
}
// Combined 256x256 weight transposes: grid (256, 4). y selects weight.
__global__ void __launch_bounds__(256)
wtrans4(const float* __restrict__ Wq, const float* __restrict__ Wk,
        const float* __restrict__ Wv, const float* __restrict__ Wm,
        bf16* wqh, bf16* wql, bf16* wkvh, bf16* wkvl, bf16* wmh, bf16* wml) {
    const int idx = blockIdx.x * 256 + threadIdx.x;
    const int n = idx >> 8, k = idx & 255;
    const int src = k * 256 + n;
    bf16 h, l;
    switch (blockIdx.y) {
        case 0: split_bf16(Wq[src], h, l); wqh[idx] = h; wql[idx] = l; break;
        case 1: split_bf16(Wk[src], h, l); wkvh[idx] = h; wkvl[idx] = l; break;
        case 2: split_bf16(Wv[src], h, l); wkvh[65536 + idx] = h; wkvl[65536 + idx] = l; break;
        default: split_bf16(Wm[src], h, l); wmh[idx] = h; wml[idx] = l; break;
    }
}
__global__ void __launch_bounds__(256)
wtrans(const float* __restrict__ W, bf16* Th, bf16* Tl, int K, int N) {
    const int idx = blockIdx.x * 256 + threadIdx.x;
    if (idx >= N * K) return;
    const int n = idx / K, k = idx - n * K;
    bf16 h, l;
    split_bf16(W[(long long)k * N + n], h, l);
    Th[idx] = h; Tl[idx] = l;
}
__global__ void __launch_bounds__(256)
ln_to_hcat(const float* __restrict__ X, const float* __restrict__ gamma,
           const float* __restrict__ beta, bf16* __restrict__ Hh, bf16* __restrict__ Hl) {
    const long long row = blockIdx.x;
    const int t = threadIdx.x;
    const float x = X[row * 256 + t];
    float s = x, q = x * x;
    #pragma unroll
    for (int o = 16; o > 0; o >>= 1) {
        s += __shfl_xor_sync(0xffffffffu, s, o);
        q += __shfl_xor_sync(0xffffffffu, q, o);
    }
    __shared__ float ss[8], qq[8];
    const int w = t >> 5;
    if ((t & 31) == 0) { ss[w] = s; qq[w] = q; }
    __syncthreads();
    s = 0.0f; q = 0.0f;
    #pragma unroll
    for (int i = 0; i < 8; i++) { s += ss[i]; q += qq[i]; }
    const float mean = s * (1.0f / 256.0f);
    const float var  = q * (1.0f / 256.0f) - mean * mean;
    const float y = (x - mean) * rsqrtf(var + 1e-5f) * gamma[t] + beta[t];
    const long long tok = gather_win((int)row);
    bf16 h, l; split_bf16(y, h, l);
    Hh[tok * 512 + 256 + t] = h; Hl[tok * 512 + 256 + t] = l;
}
__global__ void __launch_bounds__(256)
ln_res(const float* __restrict__ X, const float* __restrict__ gamma,
       const float* __restrict__ beta, const float* __restrict__ resid,
       float* __restrict__ out) {
    const long long row = blockIdx.x;
    const int t = threadIdx.x;
    const float x = X[row * 256 + t];
    float s = x, q = x * x;
    #pragma unroll
    for (int o = 16; o > 0; o >>= 1) {
        s += __shfl_xor_sync(0xffffffffu, s, o);
        q += __shfl_xor_sync(0xffffffffu, q, o);
    }
    __shared__ float ss[8], qq[8];
    const int w = t >> 5;
    if ((t & 31) == 0) { ss[w] = s; qq[w] = q; }
    __syncthreads();
    s = 0.0f; q = 0.0f;
    #pragma unroll
    for (int i = 0; i < 8; i++) { s += ss[i]; q += qq[i]; }
    const float mean = s * (1.0f / 256.0f);
    const float var  = q * (1.0f / 256.0f) - mean * mean;
    const float y = (x - mean) * rsqrtf(var + 1e-5f) * gamma[t] + beta[t];
    out[row * 256 + t] = y + resid[row * 256 + t];
}

// ===================== launch ===============================================
extern "C" void kernel_launch(void* const* d_in, const int* in_sizes, int n_in,
                              void* d_out, int out_size)
{
    const float* source = (const float*)d_in[0];
    const float* target = (const float*)d_in[1];
    const float* mask   = (const float*)d_in[2];
    const float* Wq     = (const float*)d_in[3];
    const float* Wk     = (const float*)d_in[4];
    const float* Wv     = (const float*)d_in[5];
    const float* Wmerge = (const float*)d_in[6];
    const float* gamma1 = (const float*)d_in[7];
    const float* beta1  = (const float*)d_in[8];
    const float* W1     = (const float*)d_in[9];
    const float* W2     = (const float*)d_in[10];
    const float* gamma2 = (const float*)d_in[11];
    const float* beta2  = (const float*)d_in[12];
    float* out = (float*)d_out;

    bf16 *swh, *swl, *twh, *twl, *qh, *ql, *kh, *kl, *vth, *vtl;
    bf16 *ah, *al, *hch, *hcl, *hih, *hil;
    bf16 *wqh, *wql, *wkvh, *wkvl, *wmh, *wml, *w1h, *w1l, *w2h, *w2l;
    float *msg, *msg2;
    cudaGetSymbolAddress((void**)&swh, g_swh); cudaGetSymbolAddress((void**)&swl, g_swl);
    cudaGetSymbolAddress((void**)&twh, g_twh); cudaGetSymbolAddress((void**)&twl, g_twl);
    cudaGetSymbolAddress((void**)&qh,  g_qh);  cudaGetSymbolAddress((void**)&ql,  g_ql);
    cudaGetSymbolAddress((void**)&kh,  g_kh);  cudaGetSymbolAddress((void**)&kl,  g_kl);
    cudaGetSymbolAddress((void**)&vth, g_vth); cudaGetSymbolAddress((void**)&vtl, g_vtl);
    cudaGetSymbolAddress((void**)&ah,  g_ah);  cudaGetSymbolAddress((void**)&al,  g_al);
    cudaGetSymbolAddress((void**)&msg, g_msg);
    cudaGetSymbolAddress((void**)&hch, g_hch); cudaGetSymbolAddress((void**)&hcl, g_hcl);
    cudaGetSymbolAddress((void**)&hih, g_hih); cudaGetSymbolAddress((void**)&hil, g_hil);
    cudaGetSymbolAddress((void**)&msg2, g_msg2);
    cudaGetSymbolAddress((void**)&wqh, g_wqh); cudaGetSymbolAddress((void**)&wql, g_wql);
    cudaGetSymbolAddress((void**)&wkvh, g_wkvh); cudaGetSymbolAddress((void**)&wkvl, g_wkvl);
    cudaGetSymbolAddress((void**)&wmh, g_wmh); cudaGetSymbolAddress((void**)&wml, g_wml);
    cudaGetSymbolAddress((void**)&w1h, g_w1h); cudaGetSymbolAddress((void**)&w1l, g_w1l);
    cudaGetSymbolAddress((void**)&w2h, g_w2h); cudaGetSymbolAddress((void**)&w2l, g_w2l);

    cudaFuncSetAttribute(gemm_mma<0>, cudaFuncAttributeMaxDynamicSharedMemorySize, SMEM_BYTES);
    cudaFuncSetAttribute(gemm_mma<3>, cudaFuncAttributeMaxDynamicSharedMemorySize, SMEM_BYTES);
    cudaFuncSetAttribute(gemm_mma<5>, cudaFuncAttributeMaxDynamicSharedMemorySize, SMEM_BYTES);
    cudaFuncSetAttribute(gemm_mma<6>, cudaFuncAttributeMaxDynamicSharedMemorySize, SMEM_BYTES);
    cudaFuncSetAttribute(fused_attn,  cudaFuncAttributeMaxDynamicSharedMemorySize, FA_SMEM);

    // conversions (merged launches)
    prep_st<<<dim3(TOK, 2), 256>>>(source, target, swh, swl, hch, hcl, twh, twl);
    wtrans4<<<dim3(256, 4), 256>>>(Wq, Wk, Wv, Wmerge, wqh, wql, wkvh, wkvl, wmh, wml);
    wtrans<<<(HID * 512 + 255) / 256, 256>>>(W1, w1h, w1l, 512, HID);
    wtrans<<<(D * HID + 255) / 256, 256>>>(W2, w2h, w2l, HID, D);

    // Q projection (scaled 1/16, hi/lo)
    gemm_mma<5><<<dim3(2, 256, 1), 256, SMEM_BYTES>>>(swh, swl, wqh, wql,
        nullptr, qh, ql, TOK, D, D, 0, 0, 0);
    // K + V^T combined projection (N=512)
    gemm_mma<6><<<dim3(4, 256, 1), 256, SMEM_BYTES>>>(twh, twl, wkvh, wkvl,
        nullptr, kh, kl, TOK, 512, D, 0, 0, 0);

    // fused attention
    fused_attn<<<dim3(16, 32), 256, FA_SMEM>>>(qh, ql, kh, kl, vth, vtl, mask, ah, al);

    // merge projection
    gemm_mma<0><<<dim3(2, 256, 1), 256, SMEM_BYTES>>>(ah, al, wmh, wml,
        msg, nullptr, nullptr, TOK, D, D, 0, 0, 0);
    ln_to_hcat<<<TOK, 256>>>(msg, gamma1, beta1, hch, hcl);
    // MLP1 with exact GELU
    gemm_mma<3><<<dim3(16, 256, 1), 256, SMEM_BYTES>>>(hch, hcl, w1h, w1l,
        nullptr, hih, hil, TOK, HID, 512, 0, 0, 0);
    // MLP2
    gemm_mma<0><<<dim3(2, 256, 1), 256, SMEM_BYTES>>>(hih, hil, w2h, w2l,
        msg2, nullptr, nullptr, TOK, D, HID, 0, 0, 0);
    // LN2 + residual
    ln_res<<<TOK, 256>>>(msg2, gamma2, beta2, source, out);
}

// round 10
// speedup vs baseline: 1.9498x; 1.0184x over previous
#include <cuda_runtime.h>
#include <cuda_bf16.h>
#include <math.h>
#include <stdint.h>

#define DI __device__ __forceinline__

// Fixed problem shapes (b=2, h=w=128, d=256, ns=4, f=4)
static constexpr int TOK  = 32768;
static constexpr int D    = 256;
static constexpr int L    = 1024;
static constexpr int NWIN = 32;
static constexpr int HID  = 2048;

typedef __nv_bfloat16 bf16;

// ===================== PTX helpers (base sm_103 legal: sm_80 era) ===========
DI uint32_t smem_to_u32(const void* p) {
    uint32_t a;
    asm("{ .reg .u64 t; cvta.to.shared.u64 t, %1; cvt.u32.u64 %0, t; }"
        : "=r"(a) : "l"(p));
    return a;
}
DI void ldsm4(uint32_t* r, uint32_t addr) {
    asm volatile("ldmatrix.sync.aligned.m8n8.x4.shared.b16 {%0,%1,%2,%3}, [%4];"
                 : "=r"(r[0]), "=r"(r[1]), "=r"(r[2]), "=r"(r[3]) : "r"(addr));
}
DI void mma_bf16(float* d, const uint32_t* a, const uint32_t* b) {
    asm volatile("mma.sync.aligned.m16n8k16.row.col.f32.bf16.bf16.f32 "
                 "{%0,%1,%2,%3}, {%4,%5,%6,%7}, {%8,%9}, {%0,%1,%2,%3};"
                 : "+f"(d[0]), "+f"(d[1]), "+f"(d[2]), "+f"(d[3])
                 : "r"(a[0]), "r"(a[1]), "r"(a[2]), "r"(a[3]), "r"(b[0]), "r"(b[1]));
}
DI void cpasync16(uint32_t dst, const void* src) {
    asm volatile("cp.async.cg.shared.global [%0], [%1], 16;" :: "r"(dst), "l"(src));
}
DI void cpcommit() { asm volatile("cp.async.commit_group;" ::: "memory"); }
template<int N> DI void cpwait() { asm volatile("cp.async.wait_group %0;" :: "n"(N) : "memory"); }

// ===================== index math + misc ====================================
DI int gather_win(int r) {
    int w = r >> 10, p = r & 1023;
    int b = w >> 4, wi = (w >> 2) & 3, wj = w & 3;
    int rr = p >> 5, cc = p & 31;
    int i = (wi * 32 + rr + 16) & 127;
    int j = (wj * 32 + cc + 16) & 127;
    return (b << 14) + (i << 7) + j;
}
DI float gelu_exact(float x) { return 0.5f * x * (1.0f + erff(x * 0.70710678118654752f)); }
DI void split_bf16(float x, bf16& h, bf16& l) {
    h = __float2bfloat16(x);
    l = __float2bfloat16(x - __bfloat162float(h));
}

// ===================== device scratch (no allocations) ======================
__device__ __align__(16) bf16 g_swh[TOK * D],  g_swl[TOK * D];     // source, window order
__device__ __align__(16) bf16 g_twh[TOK * D],  g_twl[TOK * D];     // target, window order
__device__ __align__(16) bf16 g_qh[TOK * D],   g_ql[TOK * D];      // Q/16, window order
__device__ __align__(16) bf16 g_kh[TOK * D],   g_kl[TOK * D];
__device__ __align__(16) bf16 g_vth[TOK * D],  g_vtl[TOK * D];     // V^T per window [win][256][1024]
__device__ __align__(16) bf16 g_ah[TOK * D],   g_al[TOK * D];      // attn out (window order)
__device__ float g_msg[TOK * D];
__device__ __align__(16) bf16 g_hch[TOK * 512], g_hcl[TOK * 512];  // hcat [TOK,512] token order
__device__ __align__(16) bf16 g_hih[(size_t)TOK * HID], g_hil[(size_t)TOK * HID];
__device__ float g_msg2[TOK * D];
__device__ __align__(16) bf16 g_wqh[D * D], g_wql[D * D];
__device__ __align__(16) bf16 g_wkvh[512 * D], g_wkvl[512 * D];    // [Wk^T ; Wv^T]
__device__ __align__(16) bf16 g_wmh[D * D], g_wml[D * D];
__device__ __align__(16) bf16 g_w1h[HID * 512], g_w1l[HID * 512];  // W1^T [2048,512]
__device__ __align__(16) bf16 g_w2h[D * HID],   g_w2l[D * HID];    // W2^T [256,2048]

// ===================== HMMA GEMM ============================================
// NT GEMM: C[M,N] = A[M,K] @ B[N,K]^T, bf16 hi/lo 3-pass split, fp32 accum.
// CTA tile 128x128, 8 warps (2Mx4N), warp tile 64x32, K-chunk 32, double buffer.
static constexpr int TILE_B  = 10240;   // 128 rows * 80B (padded stride, conflict-free)
static constexpr int STAGE_B = 4 * TILE_B;
static constexpr int SMEM_BYTES = 2 * STAGE_B;  // 81920

DI void stage_load(uint32_t sdst,
                   const bf16* __restrict__ Ah, const bf16* __restrict__ Al,
                   const bf16* __restrict__ Bh, const bf16* __restrict__ Bl,
                   int arow, int brow, int K, int k0, int t) {
    #pragma unroll
    for (int h = 0; h < 2; h++) {
        const int idx = t + h * 256;
        const int r = idx >> 2, c = (idx & 3) << 3;   // c in bf16 elements
        const uint32_t so = sdst + r * 80 + c * 2;
        const long long ga = (long long)(arow + r) * K + k0 + c;
        const long long gb = (long long)(brow + r) * K + k0 + c;
        cpasync16(so,              Ah + ga);
        cpasync16(so + TILE_B,     Al + ga);
        cpasync16(so + 2 * TILE_B, Bh + gb);
        cpasync16(so + 3 * TILE_B, Bl + gb);
    }
}

// EPI: 0=fp32, 3=gelu->bf16 hi/lo, 5=bf16 hi/lo scaled 1/16 (Q),
//      6=combined K (cols<256, hi/lo ld=256) | V^T per-window (cols>=256)
template<int EPI>
__global__ void __launch_bounds__(256, 2)
gemm_mma(const bf16* __restrict__ Ahi, const bf16* __restrict__ Alo,
         const bf16* __restrict__ Bhi, const bf16* __restrict__ Blo,
         float* __restrict__ Cf, bf16* __restrict__ Chi, bf16* __restrict__ Clo,
         int M, int N, int K, long long sA, long long sB, long long sC)
{
    extern __shared__ __align__(128) char sm[];
    const uint32_t sb = smem_to_u32(sm);
    const int t = threadIdx.x, lane = t & 31, wid = t >> 5;
    const int wm = wid >> 2, wn = wid & 3;          // 2 x 4 warp grid
    const int bn = blockIdx.x, bm = blockIdx.y, bz = blockIdx.z;
    Ahi += (long long)bz * sA; Alo += (long long)bz * sA;
    Bhi += (long long)bz * sB; Blo += (long long)bz * sB;
    const int arow = bm * 128, brow = bn * 128;

    const uint32_t aoff = (uint32_t)((wm * 64 + (lane & 7) + ((lane >> 3) & 1) * 8) * 80
                                     + (((lane >> 4) & 1) * 8) * 2);
    const uint32_t boff = (uint32_t)((wn * 32 + (lane & 7) + ((lane >> 4) & 1) * 8) * 80
                                     + (((lane >> 3) & 1) * 8) * 2);

    float acc[4][4][4];
    #pragma unroll
    for (int i = 0; i < 4; i++)
        #pragma unroll
        for (int j = 0; j < 4; j++)
            #pragma unroll
            for (int e = 0; e < 4; e++) acc[i][j][e] = 0.0f;

    const int NC = K >> 5;
    stage_load(sb, Ahi, Alo, Bhi, Blo, arow, brow, K, 0, t);
    cpcommit();

    for (int c = 0; c < NC; c++) {
        const uint32_t cur = sb + (uint32_t)(c & 1) * STAGE_B;
        if (c + 1 < NC) {
            stage_load(sb + (uint32_t)((c + 1) & 1) * STAGE_B,
                       Ahi, Alo, Bhi, Blo, arow, brow, K, (c + 1) << 5, t);
            cpcommit();
            cpwait<1>();
        } else {
            cpwait<0>();
        }
        __syncthreads();

        #pragma unroll
        for (int k16 = 0; k16 < 2; k16++) {
            uint32_t ah[4][4], al[4][4], bh[2][4], bl[2][4];
            #pragma unroll
            for (int mi = 0; mi < 4; mi++) {
                ldsm4(ah[mi], cur + aoff + mi * (16 * 80) + k16 * 32);
                ldsm4(al[mi], cur + TILE_B + aoff + mi * (16 * 80) + k16 * 32);
            }
            #pragma unroll
            for (int p = 0; p < 2; p++) {
                ldsm4(bh[p], cur + 2 * TILE_B + boff + p * (16 * 80) + k16 * 32);
                ldsm4(bl[p], cur + 3 * TILE_B + boff + p * (16 * 80) + k16 * 32);
            }
            #pragma unroll
            for (int mi = 0; mi < 4; mi++)
                #pragma unroll
                for (int ni = 0; ni < 4; ni++) {
                    const uint32_t* fh = &bh[ni >> 1][(ni & 1) * 2];
                    const uint32_t* fl = &bl[ni >> 1][(ni & 1) * 2];
                    mma_bf16(acc[mi][ni], ah[mi], fh);
                    mma_bf16(acc[mi][ni], ah[mi], fl);
                    mma_bf16(acc[mi][ni], al[mi], fh);
                }
        }
        __syncthreads();
    }

    const int group = lane >> 2, tid4 = lane & 3;
    #pragma unroll
    for (int mi = 0; mi < 4; mi++) {
        #pragma unroll
        for (int ni = 0; ni < 4; ni++) {
            const int r0 = bm * 128 + wm * 64 + mi * 16 + group;
            const int c0 = bn * 128 + wn * 32 + ni * 8 + tid4 * 2;
            const float* d = acc[mi][ni];
            if (EPI == 0) {
                float* Cp = Cf + (long long)bz * sC;
                *(float2*)(Cp + (long long)r0 * N + c0)       = make_float2(d[0], d[1]);
                *(float2*)(Cp + (long long)(r0 + 8) * N + c0) = make_float2(d[2], d[3]);
            } else if (EPI == 3 || EPI == 5) {
                #pragma unroll
                for (int rr = 0; rr < 2; rr++) {
                    float f0 = d[rr * 2], f1 = d[rr * 2 + 1];
                    if (EPI == 3) { f0 = gelu_exact(f0); f1 = gelu_exact(f1); }
                    if (EPI == 5) { f0 *= 0.0625f; f1 *= 0.0625f; }
                    bf16 h0, l0, h1, l1;
                    split_bf16(f0, h0, l0);
                    split_bf16(f1, h1, l1);
                    const long long base = (long long)bz * sC + (long long)(r0 + rr * 8) * N + c0;
                    __nv_bfloat162 hh; hh.x = h0; hh.y = h1;
                    __nv_bfloat162 ll; ll.x = l0; ll.y = l1;
                    *(__nv_bfloat162*)(Chi + base) = hh;
                    *(__nv_bfloat162*)(Clo + base) = ll;
                }
            } else { // EPI == 6
                if (c0 < 256) {
                    #pragma unroll
                    for (int rr = 0; rr < 2; rr++) {
                        bf16 h0, l0, h1, l1;
                        split_bf16(d[rr * 2], h0, l0);
                        split_bf16(d[rr * 2 + 1], h1, l1);
                        const long long base = (long long)(r0 + rr * 8) * 256 + c0;
                        __nv_bfloat162 hh; hh.x = h0; hh.y = h1;
                        __nv_bfloat162 ll; ll.x = l0; ll.y = l1;
                        *(__nv_bfloat162*)(Chi + base) = hh;
                        *(__nv_bfloat162*)(Clo + base) = ll;
                    }
                } else {
                    #pragma unroll
                    for (int rr = 0; rr < 2; rr++) {
                        const int r = r0 + rr * 8;
                        const int win = r >> 10, ml = r & 1023;
                        #pragma unroll
                        for (int e = 0; e < 2; e++) {
                            bf16 hh, ll;
                            split_bf16(d[rr * 2 + e], hh, ll);
                            const long long o = (long long)win * 262144
                                              + (long long)(c0 - 256 + e) * 1024 + ml;
                            g_vth[o] = hh; g_vtl[o] = ll;
                        }
                    }
                }
            }
        }
    }
}

// ===================== fused flash attention ================================
// Grid (16 qtiles, 32 windows), 256 threads. Q tile 64 rows; K tiles of 128.
static constexpr int FA_QH   = 0;                 // 64 x 528
static constexpr int FA_QL   = 33792;             // 64 x 528
static constexpr int FA_K    = 67584;             // 2 stages x (hi 10240 + lo 10240)
static constexpr int FA_V    = 108544;            // 2 stages x (hi 20480 + lo 20480)
static constexpr int FA_P    = 190464;            // Ph 17408 + Pl 17408
static constexpr int FA_RED  = 225280;            // 4 x 64 floats
static constexpr int FA_SMEM = 226304;

DI void fa_load_k(uint32_t sb, int stage, const bf16* __restrict__ Kh,
                  const bf16* __restrict__ Kl, int win, int kt, int dc, int t) {
    const long long base = (long long)win * 1024 + kt * 128;
    const uint32_t d0 = sb + FA_K + (uint32_t)stage * 20480;
    #pragma unroll
    for (int i = 0; i < 2; i++) {
        const int idx = t + i * 256;
        const int r = idx >> 2, c16 = idx & 3;
        const long long g = (base + r) * 256 + dc * 32 + c16 * 8;
        cpasync16(d0 + r * 80 + c16 * 16,         Kh + g);
        cpasync16(d0 + 10240 + r * 80 + c16 * 16, Kl + g);
    }
    cpcommit();
}
DI void fa_load_v(uint32_t sb, int stage, const bf16* __restrict__ Vh,
                  const bf16* __restrict__ Vl, int win, int kt, int vc, int t) {
    const uint32_t d0 = sb + FA_V + (uint32_t)stage * 40960;
    const long long base = (long long)win * 262144;
    #pragma unroll
    for (int i = 0; i < 4; i++) {
        const int idx = t + i * 256;
        const int r = idx >> 2, c16 = idx & 3;
        const long long g = base + (long long)r * 1024 + kt * 128 + vc * 32 + c16 * 8;
        cpasync16(d0 + r * 80 + c16 * 16,         Vh + g);
        cpasync16(d0 + 20480 + r * 80 + c16 * 16, Vl + g);
    }
    cpcommit();
}

__global__ void __launch_bounds__(256, 1)
fused_attn(const bf16* __restrict__ Qh, const bf16* __restrict__ Ql,
           const bf16* __restrict__ Kh, const bf16* __restrict__ Kl,
           const bf16* __restrict__ Vth, const bf16* __restrict__ Vtl,
           const float* __restrict__ mask,
           bf16* __restrict__ Oh, bf16* __restrict__ Ol)
{
    extern __shared__ __align__(128) char sm[];
    const uint32_t sb = smem_to_u32(sm);
    const int t = threadIdx.x, lane = t & 31, wid = t >> 5;
    const int wm = wid >> 2, wn = wid & 3;
    const int group = lane >> 2, tid4 = lane & 3;
    const int qt = blockIdx.x, win = blockIdx.y;
    float* red = (float*)(sm + FA_RED);

    {
        const long long qbase = (long long)win * 1024 + qt * 64;
        #pragma unroll
        for (int i = 0; i < 8; i++) {
            const int idx = t + i * 256;
            const int r = idx >> 5, c16 = idx & 31;
            const uint32_t d = sb + FA_QH + r * 528 + c16 * 16;
            const long long g = (qbase + r) * 256 + c16 * 8;
            cpasync16(d, Qh + g);
            cpasync16(d + (FA_QL - FA_QH), Ql + g);
        }
        cpcommit();
    }

    const uint32_t aQ  = sb + FA_QH + (uint32_t)((wm * 32 + (lane & 7) + ((lane >> 3) & 1) * 8) * 528
                                                 + ((lane >> 4) & 1) * 16);
    const uint32_t aQl = aQ + (FA_QL - FA_QH);
    const uint32_t bKr = (uint32_t)((wn * 32 + (lane & 7) + ((lane >> 4) & 1) * 8) * 80
                                    + ((lane >> 3) & 1) * 16);
    const uint32_t bVr = (uint32_t)((wn * 64 + (lane & 7) + ((lane >> 4) & 1) * 8) * 80
                                    + ((lane >> 3) & 1) * 16);
    const uint32_t aP  = sb + FA_P + (uint32_t)((wm * 32 + (lane & 7) + ((lane >> 3) & 1) * 8) * 272
                                                + ((lane >> 4) & 1) * 16);

    float acc_o[2][8][4];
    #pragma unroll
    for (int mi = 0; mi < 2; mi++)
        #pragma unroll
        for (int nj = 0; nj < 8; nj++)
            #pragma unroll
            for (int e = 0; e < 4; e++) acc_o[mi][nj][e] = 0.0f;
    float m_p[2][2] = {{-1e30f, -1e30f}, {-1e30f, -1e30f}};
    float l_p[2][2] = {{0.0f, 0.0f}, {0.0f, 0.0f}};

    fa_load_k(sb, 0, Kh, Kl, win, 0, 0, t);

    for (int kt = 0; kt < 8; kt++) {
        float acc_s[2][4][4];
        #pragma unroll
        for (int mi = 0; mi < 2; mi++)
            #pragma unroll
            for (int ni = 0; ni < 4; ni++)
                #pragma unroll
                for (int e = 0; e < 4; e++) acc_s[mi][ni][e] = 0.0f;

        // prefetch mask tile for this kt into registers (hidden under QK MMAs)
        float2 marr[2][4][2];
        {
            const float* mrow = mask + (long long)(win & 15) * 1048576;
            #pragma unroll
            for (int mi = 0; mi < 2; mi++)
                #pragma unroll
                for (int ni = 0; ni < 4; ni++)
                    #pragma unroll
                    for (int rr = 0; rr < 2; rr++) {
                        const int rg = qt * 64 + wm * 32 + mi * 16 + rr * 8 + group;
                        const int cg = kt * 128 + wn * 32 + ni * 8 + tid4 * 2;
                        marr[mi][ni][rr] = *(const float2*)(mrow + (long long)rg * 1024 + cg);
                    }
        }

        for (int dc = 0; dc < 8; dc++) {
            if (dc < 7) fa_load_k(sb, (dc + 1) & 1, Kh, Kl, win, kt, dc + 1, t);
            else        fa_load_v(sb, 0, Vth, Vtl, win, kt, 0, t);
            cpwait<1>();
            __syncthreads();
            const uint32_t kb = sb + FA_K + (uint32_t)((dc & 1) * 20480);
            #pragma unroll
            for (int kk = 0; kk < 2; kk++) {
                uint32_t qhf[2][4], qlf[2][4], khf[2][4], klf[2][4];
                #pragma unroll
                for (int mi = 0; mi < 2; mi++) {
                    ldsm4(qhf[mi], aQ  + mi * (16 * 528) + dc * 64 + kk * 32);
                    ldsm4(qlf[mi], aQl + mi * (16 * 528) + dc * 64 + kk * 32);
                }
                #pragma unroll
                for (int p = 0; p < 2; p++) {
                    ldsm4(khf[p], kb + bKr + p * (16 * 80) + kk * 32);
                    ldsm4(klf[p], kb + 10240 + bKr + p * (16 * 80) + kk * 32);
                }
                #pragma unroll
                for (int mi = 0; mi < 2; mi++)
                    #pragma unroll
                    for (int ni = 0; ni < 4; ni++) {
                        const uint32_t* fh = &khf[ni >> 1][(ni & 1) * 2];
                        const uint32_t* fl = &klf[ni >> 1][(ni & 1) * 2];
                        mma_bf16(acc_s[mi][ni], qhf[mi], fh);
                        mma_bf16(acc_s[mi][ni], qhf[mi], fl);
                        mma_bf16(acc_s[mi][ni], qlf[mi], fh);
                    }
            }
            __syncthreads();
        }

        // ---- mask add (from prefetched registers) + online softmax
        #pragma unroll
        for (int mi = 0; mi < 2; mi++)
            #pragma unroll
            for (int ni = 0; ni < 4; ni++)
                #pragma unroll
                for (int rr = 0; rr < 2; rr++) {
                    acc_s[mi][ni][rr * 2 + 0] += marr[mi][ni][rr].x;
                    acc_s[mi][ni][rr * 2 + 1] += marr[mi][ni][rr].y;
                }
        #pragma unroll
        for (int mi = 0; mi < 2; mi++)
            #pragma unroll
            for (int rr = 0; rr < 2; rr++) {
                float v = -1e30f;
                #pragma unroll
                for (int ni = 0; ni < 4; ni++)
                    v = fmaxf(v, fmaxf(acc_s[mi][ni][rr * 2], acc_s[mi][ni][rr * 2 + 1]));
                v = fmaxf(v, __shfl_xor_sync(0xffffffffu, v, 1));
                v = fmaxf(v, __shfl_xor_sync(0xffffffffu, v, 2));
                if (tid4 == 0) red[wn * 64 + wm * 32 + mi * 16 + rr * 8 + group] = v;
            }
        __syncthreads();
        float scl[2][2], lsum[2][2] = {{0.0f, 0.0f}, {0.0f, 0.0f}};
        #pragma unroll
        for (int mi = 0; mi < 2; mi++)
            #pragma unroll
            for (int rr = 0; rr < 2; rr++) {
                const int r64 = wm * 32 + mi * 16 + rr * 8 + group;
                const float mt = fmaxf(fmaxf(red[r64], red[64 + r64]),
                                       fmaxf(red[128 + r64], red[192 + r64]));
                const float mn = fmaxf(m_p[mi][rr], mt);
                scl[mi][rr] = __expf(m_p[mi][rr] - mn);
                m_p[mi][rr] = mn;
            }
        #pragma unroll
        for (int mi = 0; mi < 2; mi++)
            #pragma unroll
            for (int ni = 0; ni < 4; ni++)
                #pragma unroll
                for (int rr = 0; rr < 2; rr++) {
                    const float p0 = __expf(acc_s[mi][ni][rr * 2]     - m_p[mi][rr]);
                    const float p1 = __expf(acc_s[mi][ni][rr * 2 + 1] - m_p[mi][rr]);
                    lsum[mi][rr] += p0 + p1;
                    bf16 h0, l0, h1, l1;
                    split_bf16(p0, h0, l0);
                    split_bf16(p1, h1, l1);
                    const int r64 = wm * 32 + mi * 16 + rr * 8 + group;
                    const int cb = (wn * 32 + ni * 8 + tid4 * 2) * 2;
                    __nv_bfloat162 hh; hh.x = h0; hh.y = h1;
                    __nv_bfloat162 ll; ll.x = l0; ll.y = l1;
                    *(__nv_bfloat162*)(sm + FA_P + r64 * 272 + cb)         = hh;
                    *(__nv_bfloat162*)(sm + FA_P + 17408 + r64 * 272 + cb) = ll;
                }
        #pragma unroll
        for (int mi = 0; mi < 2; mi++)
            #pragma unroll
            for (int rr = 0; rr < 2; rr++)
                l_p[mi][rr] = l_p[mi][rr] * scl[mi][rr] + lsum[mi][rr];
        #pragma unroll
        for (int mi = 0; mi < 2; mi++)
            #pragma unroll
            for (int nj = 0; nj < 8; nj++)
                #pragma unroll
                for (int e = 0; e < 4; e++)
                    acc_o[mi][nj][e] *= scl[mi][e >> 1];

        for (int vc = 0; vc < 4; vc++) {
            if (vc < 3)      fa_load_v(sb, (vc + 1) & 1, Vth, Vtl, win, kt, vc + 1, t);
            else if (kt < 7) fa_load_k(sb, 0, Kh, Kl, win, kt + 1, 0, t);
            if (vc == 3 && kt == 7) { cpwait<0>(); } else { cpwait<1>(); }
            __syncthreads();
            const uint32_t vb = sb + FA_V + (uint32_t)((vc & 1) * 40960);
            #pragma unroll
            for (int kk = 0; kk < 2; kk++) {
                uint32_t phf[2][4], plf[2][4], vhf[4][4], vlf[4][4];
                #pragma unroll
                for (int mi = 0; mi < 2; mi++) {
                    ldsm4(phf[mi], aP + mi * (16 * 272) + vc * 64 + kk * 32);
                    ldsm4(plf[mi], aP + 17408 + mi * (16 * 272) + vc * 64 + kk * 32);
                }
                #pragma unroll
                for (int p = 0; p < 4; p++) {
                    ldsm4(vhf[p], vb + bVr + p * (16 * 80) + kk * 32);
                    ldsm4(vlf[p], vb + 20480 + bVr + p * (16 * 80) + kk * 32);
                }
                #pragma unroll
                for (int mi = 0; mi < 2; mi++)
                    #pragma unroll
                    for (int nj = 0; nj < 8; nj++) {
                        const uint32_t* fh = &vhf[nj >> 1][(nj & 1) * 2];
                        const uint32_t* fl = &vlf[nj >> 1][(nj & 1) * 2];
                        mma_bf16(acc_o[mi][nj], phf[mi], fh);
                        mma_bf16(acc_o[mi][nj], phf[mi], fl);
                        mma_bf16(acc_o[mi][nj], plf[mi], fh);
                    }
            }
            __syncthreads();
        }
    }

    #pragma unroll
    for (int mi = 0; mi < 2; mi++)
        #pragma unroll
        for (int rr = 0; rr < 2; rr++) {
            float v = l_p[mi][rr];
            v += __shfl_xor_sync(0xffffffffu, v, 1);
            v += __shfl_xor_sync(0xffffffffu, v, 2);
            if (tid4 == 0) red[wn * 64 + wm * 32 + mi * 16 + rr * 8 + group] = v;
        }
    __syncthreads();
    float inv[2][2];
    #pragma unroll
    for (int mi = 0; mi < 2; mi++)
        #pragma unroll
        for (int rr = 0; rr < 2; rr++) {
            const int r64 = wm * 32 + mi * 16 + rr * 8 + group;
            inv[mi][rr] = 1.0f / (red[r64] + red[64 + r64] + red[128 + r64] + red[192 + r64]);
        }
    const long long obase = (long long)win * 1024 + qt * 64;
    #pragma unroll
    for (int mi = 0; mi < 2; mi++)
        #pragma unroll
        for (int nj = 0; nj < 8; nj++) {
            const int r0 = wm * 32 + mi * 16 + group;
            const int c0 = wn * 64 + nj * 8 + tid4 * 2;
            #pragma unroll
            for (int rr = 0; rr < 2; rr++) {
                const float f0 = acc_o[mi][nj][rr * 2]     * inv[mi][rr];
                const float f1 = acc_o[mi][nj][rr * 2 + 1] * inv[mi][rr];
                bf16 h0, l0, h1, l1;
                split_bf16(f0, h0, l0);
                split_bf16(f1, h1, l1);
                const long long o = (obase + r0 + rr * 8) * 256 + c0;
                __nv_bfloat162 hh; hh.x = h0; hh.y = h1;
                __nv_bfloat162 ll; ll.x = l0; ll.y = l1;
                *(__nv_bfloat162*)(Oh + o) = hh;
                *(__nv_bfloat162*)(Ol + o) = ll;
            }
        }
}

// ===================== elementwise kernels ==================================
__global__ void __launch_bounds__(256)
prep_st(const float* __restrict__ src, const float* __restrict__ tgt,
        bf16* swh, bf16* swl, bf16* hch, bf16* hcl, bf16* twh, bf16* twl) {
    const int r = blockIdx.x, c = threadIdx.x;
    bf16 h, l;
    if (blockIdx.y == 0) {
        split_bf16(src[(long long)gather_win(r) * 256 + c], h, l);
        swh[(long long)r * 256 + c] = h; swl[(long long)r * 256 + c] = l;
        split_bf16(src[(long long)r * 256 + c], h, l);
        hch[(long long)r * 512 + c] = h; hcl[(long long)r * 512 + c] = l;
    } else {
        split_bf16(tgt[(long long)gather_win(r) * 256 + c], h, l);
        twh[(long long)r * 256 + c] = h; twl[(long long)r * 256 + c] = l;
    }
}
__global__ void __launch_bounds__(256)
wtrans4(const float* __restrict__ Wq, const float* __restrict__ Wk,
        const float* __restrict__ Wv, const float* __restrict__ Wm,
        bf16* wqh, bf16* wql, bf16* wkvh, bf16* wkvl, bf16* wmh, bf16* wml) {
    const int idx = blockIdx.x * 256 + threadIdx.x;
    const int n = idx >> 8, k = idx & 255;
    const int src = k * 256 + n;
    bf16 h, l;
    switch (blockIdx.y) {
        case 0: split_bf16(Wq[src], h, l); wqh[idx] = h; wql[idx] = l; break;
        case 1: split_bf16(Wk[src], h, l); wkvh[idx] = h; wkvl[idx] = l; break;
        case 2: split_bf16(Wv[src], h, l); wkvh[65536 + idx] = h; wkvl[65536 + idx] = l; break;
        default: split_bf16(Wm[src], h, l); wmh[idx] = h; wml[idx] = l; break;
    }
}
__global__ void __launch_bounds__(256)
wtrans(const float* __restrict__ W, bf16* Th, bf16* Tl, int K, int N) {
    const int idx = blockIdx.x * 256 + threadIdx.x;
    if (idx >= N * K) return;
    const int n = idx / K, k = idx - n * K;
    bf16 h, l;
    split_bf16(W[(long long)k * N + n], h, l);
    Th[idx] = h; Tl[idx] = l;
}
__global__ void __launch_bounds__(256)
ln_to_hcat(const float* __restrict__ X, const float* __restrict__ gamma,
           const float* __restrict__ beta, bf16* __restrict__ Hh, bf16* __restrict__ Hl) {
    const long long row = blockIdx.x;
    const int t = threadIdx.x;
    const float x = X[row * 256 + t];
    float s = x, q = x * x;
    #pragma unroll
    for (int o = 16; o > 0; o >>= 1) {
        s += __shfl_xor_sync(0xffffffffu, s, o);
        q += __shfl_xor_sync(0xffffffffu, q, o);
    }
    __shared__ float ss[8], qq[8];
    const int w = t >> 5;
    if ((t & 31) == 0) { ss[w] = s; qq[w] = q; }
    __syncthreads();
    s = 0.0f; q = 0.0f;
    #pragma unroll
    for (int i = 0; i < 8; i++) { s += ss[i]; q += qq[i]; }
    const float mean = s * (1.0f / 256.0f);
    const float var  = q * (1.0f / 256.0f) - mean * mean;
    const float y = (x - mean) * rsqrtf(var + 1e-5f) * gamma[t] + beta[t];
    const long long tok = gather_win((int)row);
    bf16 h, l; split_bf16(y, h, l);
    Hh[tok * 512 + 256 + t] = h; Hl[tok * 512 + 256 + t] = l;
}
__global__ void __launch_bounds__(256)
ln_res(const float* __restrict__ X, const float* __restrict__ gamma,
       const float* __restrict__ beta, const float* __restrict__ resid,
       float* __restrict__ out) {
    const long long row = blockIdx.x;
    const int t = threadIdx.x;
    const float x = X[row * 256 + t];
    float s = x, q = x * x;
    #pragma unroll
    for (int o = 16; o > 0; o >>= 1) {
        s += __shfl_xor_sync(0xffffffffu, s, o);
        q += __shfl_xor_sync(0xffffffffu, q, o);
    }
    __shared__ float ss[8], qq[8];
    const int w = t >> 5;
    if ((t & 31) == 0) { ss[w] = s; qq[w] = q; }
    __syncthreads();
    s = 0.0f; q = 0.0f;
    #pragma unroll
    for (int i = 0; i < 8; i++) { s += ss[i]; q += qq[i]; }
    const float mean = s * (1.0f / 256.0f);
    const float var  = q * (1.0f / 256.0f) - mean * mean;
    const float y = (x - mean) * rsqrtf(var + 1e-5f) * gamma[t] + beta[t];
    out[row * 256 + t] = y + resid[row * 256 + t];
}

// ===================== launch ===============================================
extern "C" void kernel_launch(void* const* d_in, const int* in_sizes, int n_in,
                              void* d_out, int out_size)
{
    const float* source = (const float*)d_in[0];
    const float* target = (const float*)d_in[1];
    const float* mask   = (const float*)d_in[2];
    const float* Wq     = (const float*)d_in[3];
    const float* Wk     = (const float*)d_in[4];
    const float* Wv     = (const float*)d_in[5];
    const float* Wmerge = (const float*)d_in[6];
    const float* gamma1 = (const float*)d_in[7];
    const float* beta1  = (const float*)d_in[8];
    const float* W1     = (const float*)d_in[9];
    const float* W2     = (const float*)d_in[10];
    const float* gamma2 = (const float*)d_in[11];
    const float* beta2  = (const float*)d_in[12];
    float* out = (float*)d_out;

    bf16 *swh, *swl, *twh, *twl, *qh, *ql, *kh, *kl, *vth, *vtl;
    bf16 *ah, *al, *hch, *hcl, *hih, *hil;
    bf16 *wqh, *wql, *wkvh, *wkvl, *wmh, *wml, *w1h, *w1l, *w2h, *w2l;
    float *msg, *msg2;
    cudaGetSymbolAddress((void**)&swh, g_swh); cudaGetSymbolAddress((void**)&swl, g_swl);
    cudaGetSymbolAddress((void**)&twh, g_twh); cudaGetSymbolAddress((void**)&twl, g_twl);
    cudaGetSymbolAddress((void**)&qh,  g_qh);  cudaGetSymbolAddress((void**)&ql,  g_ql);
    cudaGetSymbolAddress((void**)&kh,  g_kh);  cudaGetSymbolAddress((void**)&kl,  g_kl);
    cudaGetSymbolAddress((void**)&vth, g_vth); cudaGetSymbolAddress((void**)&vtl, g_vtl);
    cudaGetSymbolAddress((void**)&ah,  g_ah);  cudaGetSymbolAddress((void**)&al,  g_al);
    cudaGetSymbolAddress((void**)&msg, g_msg);
    cudaGetSymbolAddress((void**)&hch, g_hch); cudaGetSymbolAddress((void**)&hcl, g_hcl);
    cudaGetSymbolAddress((void**)&hih, g_hih); cudaGetSymbolAddress((void**)&hil, g_hil);
    cudaGetSymbolAddress((void**)&msg2, g_msg2);
    cudaGetSymbolAddress((void**)&wqh, g_wqh); cudaGetSymbolAddress((void**)&wql, g_wql);
    cudaGetSymbolAddress((void**)&wkvh, g_wkvh); cudaGetSymbolAddress((void**)&wkvl, g_wkvl);
    cudaGetSymbolAddress((void**)&wmh, g_wmh); cudaGetSymbolAddress((void**)&wml, g_wml);
    cudaGetSymbolAddress((void**)&w1h, g_w1h); cudaGetSymbolAddress((void**)&w1l, g_w1l);
    cudaGetSymbolAddress((void**)&w2h, g_w2h); cudaGetSymbolAddress((void**)&w2l, g_w2l);

    cudaFuncSetAttribute(gemm_mma<0>, cudaFuncAttributeMaxDynamicSharedMemorySize, SMEM_BYTES);
    cudaFuncSetAttribute(gemm_mma<3>, cudaFuncAttributeMaxDynamicSharedMemorySize, SMEM_BYTES);
    cudaFuncSetAttribute(gemm_mma<5>, cudaFuncAttributeMaxDynamicSharedMemorySize, SMEM_BYTES);
    cudaFuncSetAttribute(gemm_mma<6>, cudaFuncAttributeMaxDynamicSharedMemorySize, SMEM_BYTES);
    cudaFuncSetAttribute(fused_attn,  cudaFuncAttributeMaxDynamicSharedMemorySize, FA_SMEM);

    // Launch order arranged so ncu (-s 5 -c 1) profiles fused_attn (6th launch).
    prep_st<<<dim3(TOK, 2), 256>>>(source, target, swh, swl, hch, hcl, twh, twl);   // 1
    wtrans4<<<dim3(256, 4), 256>>>(Wq, Wk, Wv, Wmerge, wqh, wql, wkvh, wkvl, wmh, wml); // 2
    gemm_mma<5><<<dim3(2, 256, 1), 256, SMEM_BYTES>>>(swh, swl, wqh, wql,           // 3: Q proj
        nullptr, qh, ql, TOK, D, D, 0, 0, 0);
    gemm_mma<6><<<dim3(4, 256, 1), 256, SMEM_BYTES>>>(twh, twl, wkvh, wkvl,         // 4: K+V^T proj
        nullptr, kh, kl, TOK, 512, D, 0, 0, 0);
    wtrans<<<(HID * 512 + 255) / 256, 256>>>(W1, w1h, w1l, 512, HID);               // 5
    fused_attn<<<dim3(16, 32), 256, FA_SMEM>>>(qh, ql, kh, kl, vth, vtl, mask, ah, al); // 6 (profiled)
    wtrans<<<(D * HID + 255) / 256, 256>>>(W2, w2h, w2l, HID, D);                   // 7

    // merge projection
    gemm_mma<0><<<dim3(2, 256, 1), 256, SMEM_BYTES>>>(ah, al, wmh, wml,
        msg, nullptr, nullptr, TOK, D, D, 0, 0, 0);
    ln_to_hcat<<<TOK, 256>>>(msg, gamma1, beta1, hch, hcl);
    // MLP1 with exact GELU
    gemm_mma<3><<<dim3(16, 256, 1), 256, SMEM_BYTES>>>(hch, hcl, w1h, w1l,
        nullptr, hih, hil, TOK, HID, 512, 0, 0, 0);
    // MLP2
    gemm_mma<0><<<dim3(2, 256, 1), 256, SMEM_BYTES>>>(hih, hil, w2h, w2l,
        msg2, nullptr, nullptr, TOK, D, HID, 0, 0, 0);
    // LN2 + residual
    ln_res<<<TOK, 256>>>(msg2, gamma2, beta2, source, out);
}